// round 5
// baseline (speedup 1.0000x reference)
#include <cuda_runtime.h>
#include <math.h>

#define BATCH 2048
#define HID   512
#define WIN   24
#define LZ    514   // HID + KERNEL - 1

// ---------------- scratch (device globals; no allocations) ----------------
__device__ float g_H   [(size_t)WIN * BATCH * HID];   // conv output, [t][b][h]
__device__ float g_HiUd[(size_t)WIN * BATCH * HID];   // H[t] @ Ud^T
__device__ float g_X   [(size_t)BATCH * 1024];        // [d0 | s0] per batch row
__device__ float g_L   [(size_t)BATCH * HID];         // tanh(ds@Wd^T + HiUd)
__device__ float g_G   [(size_t)BATCH * 2048];        // d0 @ Whh^T
__device__ float g_l   [BATCH];
__device__ float g_Bw  [BATCH];
__device__ float g_yr  [BATCH];                        // y_real@w[:24] + b
__device__ float g_yf  [BATCH];
__device__ float g_ctv [HID];
__device__ float g_part[32 * HID];

// ---------------- conv + relu ----------------
__global__ void conv_kernel(const float* __restrict__ Z,
                            const float* __restrict__ conv_w,
                            const float* __restrict__ conv_b)
{
    int b = blockIdx.x;
    int h = threadIdx.x;             // 512 threads
    __shared__ float z0[LZ + 2];
    __shared__ float z1[LZ + 2];
    const float* Z0 = Z + (size_t)b * LZ;                  // c = 0
    const float* Z1 = Z + (size_t)(BATCH + b) * LZ;        // c = 1
    for (int i = h; i < LZ; i += HID) { z0[i] = Z0[i]; z1[i] = Z1[i]; }
    __syncthreads();
    float a0 = z0[h], a1 = z0[h + 1], a2 = z0[h + 2];
    float b0 = z1[h], b1 = z1[h + 1], b2 = z1[h + 2];
    #pragma unroll
    for (int t = 0; t < WIN; t++) {
        const float* cw = conv_w + t * 6;   // [t][c][k]
        float v = conv_b[t]
                + a0 * cw[0] + a1 * cw[1] + a2 * cw[2]
                + b0 * cw[3] + b1 * cw[4] + b2 * cw[5];
        g_H[((size_t)t * BATCH + b) * HID + h] = fmaxf(v, 0.f);
    }
}

// ---------------- generic fp32 GEMM: C = [tanh](A @ B^T [+ add]) ----------------
// A: [M, lda] row-major, B: [N, ldb] row-major, C: [M, ldc]
// 64x64 tile, BK=16, 256 threads, 4x4 per thread. M,N,K multiples of 64/16.
__global__ __launch_bounds__(256) void gemm64(
    const float* __restrict__ A, int lda,
    const float* __restrict__ B, int ldb,
    float*       __restrict__ C, int ldc,
    const float* __restrict__ addP, int ldadd,
    int K, int do_tanh)
{
    __shared__ float As[16][68];
    __shared__ float Bs[16][68];
    int tid = threadIdx.x;
    int tx = tid & 15, ty = tid >> 4;
    int row0 = blockIdx.y * 64, col0 = blockIdx.x * 64;
    int lr = tid >> 2;          // 0..63
    int lc = (tid & 3) * 4;     // 0,4,8,12
    const float* Ab = A + (size_t)(row0 + lr) * lda + lc;
    const float* Bb = B + (size_t)(col0 + lr) * ldb + lc;

    float acc[4][4] = {};
    for (int k0 = 0; k0 < K; k0 += 16) {
        float4 av = *(const float4*)(Ab + k0);
        float4 bv = *(const float4*)(Bb + k0);
        As[lc + 0][lr] = av.x; As[lc + 1][lr] = av.y;
        As[lc + 2][lr] = av.z; As[lc + 3][lr] = av.w;
        Bs[lc + 0][lr] = bv.x; Bs[lc + 1][lr] = bv.y;
        Bs[lc + 2][lr] = bv.z; Bs[lc + 3][lr] = bv.w;
        __syncthreads();
        #pragma unroll
        for (int k = 0; k < 16; k++) {
            float4 a = *(const float4*)&As[k][ty * 4];
            float4 b = *(const float4*)&Bs[k][tx * 4];
            float aa[4] = {a.x, a.y, a.z, a.w};
            float bb[4] = {b.x, b.y, b.z, b.w};
            #pragma unroll
            for (int i = 0; i < 4; i++)
                #pragma unroll
                for (int j = 0; j < 4; j++)
                    acc[i][j] = fmaf(aa[i], bb[j], acc[i][j]);
        }
        __syncthreads();
    }
    #pragma unroll
    for (int i = 0; i < 4; i++) {
        int r = row0 + ty * 4 + i;
        #pragma unroll
        for (int j = 0; j < 4; j++) {
            int c = col0 + tx * 4 + j;
            float v = acc[i][j];
            if (addP)    v += addP[(size_t)r * ldadd + c];
            if (do_tanh) v = tanhf(v);
            C[(size_t)r * ldc + c] = v;
        }
    }
}

// ---------------- l[b] = L[b,:] . vd ----------------
__global__ void ldot_kernel(const float* __restrict__ vd)
{
    int warp = threadIdx.x >> 5, lane = threadIdx.x & 31;
    int row = blockIdx.x * 8 + warp;
    const float* lr = g_L + (size_t)row * HID;
    float s = 0.f;
    for (int j = lane; j < HID; j += 32) s = fmaf(lr[j], vd[j], s);
    #pragma unroll
    for (int o = 16; o; o >>= 1) s += __shfl_xor_sync(0xFFFFFFFFu, s, o);
    if (!lane) g_l[row] = s;
}

// ---------------- softmax over batch (single block) ----------------
__global__ void softmax_kernel()
{
    __shared__ float red[32];
    __shared__ float sv[2];
    int tid = threadIdx.x;                 // 1024 threads
    float m = -1e30f;
    for (int i = tid; i < BATCH; i += 1024) m = fmaxf(m, g_l[i]);
    #pragma unroll
    for (int o = 16; o; o >>= 1) m = fmaxf(m, __shfl_xor_sync(0xFFFFFFFFu, m, o));
    if ((tid & 31) == 0) red[tid >> 5] = m;
    __syncthreads();
    if (tid < 32) {
        float v = red[tid];
        #pragma unroll
        for (int o = 16; o; o >>= 1) v = fmaxf(v, __shfl_xor_sync(0xFFFFFFFFu, v, o));
        if (!tid) sv[0] = v;
    }
    __syncthreads();
    m = sv[0];
    float s = 0.f;
    for (int i = tid; i < BATCH; i += 1024) s += expf(g_l[i] - m);
    #pragma unroll
    for (int o = 16; o; o >>= 1) s += __shfl_xor_sync(0xFFFFFFFFu, s, o);
    if ((tid & 31) == 0) red[tid >> 5] = s;
    __syncthreads();
    if (tid < 32) {
        float v = red[tid];
        #pragma unroll
        for (int o = 16; o; o >>= 1) v += __shfl_xor_sync(0xFFFFFFFFu, v, o);
        if (!tid) sv[1] = v;
    }
    __syncthreads();
    float inv = 1.f / sv[1];
    for (int i = tid; i < BATCH; i += 1024) g_Bw[i] = expf(g_l[i] - m) * inv;
}

// ---------------- partial Bw @ H[t] (32 blocks x 512 threads, no atomics) ----------------
__global__ void ctpart_kernel(int t)
{
    int h = threadIdx.x;
    int blk = blockIdx.x;
    const float* Ht = g_H + (size_t)t * BATCH * HID;
    float s = 0.f;
    int b0 = blk * 64;
    for (int b = b0; b < b0 + 64; b++)
        s = fmaf(g_Bw[b], Ht[(size_t)b * HID + h], s);
    g_part[blk * HID + h] = s;
}

// ---------------- ctv += partials; ys = ctv . w[24:]; y_fake = yr + ys ----------------
__global__ void yfake_kernel(const float* __restrict__ w)
{
    __shared__ float red[16];
    __shared__ float ysh;
    int h = threadIdx.x;                   // 512 threads
    float s = g_ctv[h];
    #pragma unroll
    for (int i = 0; i < 32; i++) s += g_part[i * HID + h];
    g_ctv[h] = s;
    float p = s * w[WIN + h];
    int lane = h & 31, warp = h >> 5;
    #pragma unroll
    for (int o = 16; o; o >>= 1) p += __shfl_xor_sync(0xFFFFFFFFu, p, o);
    if (!lane) red[warp] = p;
    __syncthreads();
    // Final reduce of 16 partials on a FULL warp (lanes 16..31 contribute 0):
    // previous version ran a masked shfl on a half-active warp -> deadlock.
    if (h < 32) {
        float v = (h < 16) ? red[h] : 0.f;
        #pragma unroll
        for (int o = 16; o; o >>= 1) v += __shfl_xor_sync(0xFFFFFFFFu, v, o);
        if (!h) ysh = v;
    }
    __syncthreads();
    float ys = ysh;
    for (int b = h; b < BATCH; b += HID) g_yf[b] = g_yr[b] + ys;
}

// ---------------- LSTM cell update ----------------
__device__ __forceinline__ float sigf(float x) { return 1.f / (1.f + expf(-x)); }

__global__ void lstm_kernel(const float* __restrict__ Wih,
                            const float* __restrict__ bih,
                            const float* __restrict__ bhh)
{
    int b = blockIdx.x, h = threadIdx.x;   // 2048 x 512
    float y = g_yf[b];
    const float* g = g_G + (size_t)b * 2048;
    float ig = sigf (fmaf(y, Wih[h],           bih[h]           + bhh[h])           + g[h]);
    float fg = sigf (fmaf(y, Wih[HID + h],     bih[HID + h]     + bhh[HID + h])     + g[HID + h]);
    float gg = tanhf(fmaf(y, Wih[2*HID + h],   bih[2*HID + h]   + bhh[2*HID + h])   + g[2*HID + h]);
    float og = sigf (fmaf(y, Wih[3*HID + h],   bih[3*HID + h]   + bhh[3*HID + h])   + g[3*HID + h]);
    float* X = g_X + (size_t)b * 1024;
    float ns = fg * X[HID + h] + ig * gg;
    float nd = og * tanhf(ns);
    X[h] = nd;
    X[HID + h] = ns;
}

// ---------------- init: X = [d|s], ctv = 0, yr = y_real@w[:24] + b ----------------
__global__ void init_kernel(const float* __restrict__ din,
                            const float* __restrict__ sin_,
                            const float* __restrict__ y_real,
                            const float* __restrict__ w,
                            const float* __restrict__ bparam)
{
    size_t i = (size_t)blockIdx.x * blockDim.x + threadIdx.x;   // BATCH*HID threads
    int b = (int)(i / HID), h = (int)(i % HID);
    g_X[(size_t)b * 1024 + h]       = din[i];
    g_X[(size_t)b * 1024 + HID + h] = sin_[i];
    if (i < HID) g_ctv[i] = 0.f;
    if (i < BATCH) {
        float s = bparam[0];
        #pragma unroll
        for (int k = 0; k < WIN; k++) s = fmaf(y_real[i * WIN + k], w[k], s);
        g_yr[i] = s;
    }
}

// ---------------- finalize: out = [y_fake | d0 | s0] (guarded by out_size) ----------------
__global__ void final_kernel(float* __restrict__ out, int out_size)
{
    size_t i = (size_t)blockIdx.x * blockDim.x + threadIdx.x;   // BATCH*HID threads
    if (i < BATCH && i < (size_t)out_size) out[i] = g_yf[i];
    if (out_size >= BATCH + 2 * BATCH * HID) {
        int b = (int)(i / HID), h = (int)(i % HID);
        out[BATCH + i]               = g_X[(size_t)b * 1024 + h];
        out[BATCH + BATCH * HID + i] = g_X[(size_t)b * 1024 + HID + h];
    }
}

// ---------------- launch ----------------
extern "C" void kernel_launch(void* const* d_in, const int* in_sizes, int n_in,
                              void* d_out, int out_size)
{
    const float* Z      = (const float*)d_in[0];
    const float* din    = (const float*)d_in[1];
    const float* sin_   = (const float*)d_in[2];
    const float* y_real = (const float*)d_in[3];
    const float* vd     = (const float*)d_in[4];
    const float* Wd     = (const float*)d_in[5];
    const float* Ud     = (const float*)d_in[6];
    const float* w      = (const float*)d_in[7];
    const float* bparam = (const float*)d_in[8];
    const float* conv_w = (const float*)d_in[9];
    const float* conv_b = (const float*)d_in[10];
    const float* Wih    = (const float*)d_in[11];
    const float* Whh    = (const float*)d_in[12];
    const float* bih    = (const float*)d_in[13];
    const float* bhh    = (const float*)d_in[14];

    float *pH, *pHiUd, *pX, *pL, *pG;
    cudaGetSymbolAddress((void**)&pH,    g_H);
    cudaGetSymbolAddress((void**)&pHiUd, g_HiUd);
    cudaGetSymbolAddress((void**)&pX,    g_X);
    cudaGetSymbolAddress((void**)&pL,    g_L);
    cudaGetSymbolAddress((void**)&pG,    g_G);

    // Precompute: conv, H@Ud^T (all 24 steps as one GEMM), init states
    conv_kernel<<<BATCH, HID>>>(Z, conv_w, conv_b);
    gemm64<<<dim3(HID / 64, WIN * BATCH / 64), 256>>>(
        pH, HID, Ud, HID, pHiUd, HID, nullptr, 0, HID, 0);
    init_kernel<<<BATCH * HID / 256, 256>>>(din, sin_, y_real, w, bparam);

    for (int t = 0; t < WIN; t++) {
        // L = tanh([d0|s0] @ Wd^T + HiUd[t])
        gemm64<<<dim3(HID / 64, BATCH / 64), 256>>>(
            pX, 1024, Wd, 1024, pL, HID,
            pHiUd + (size_t)t * BATCH * HID, HID, 1024, 1);
        // G = d0 @ Whh^T
        gemm64<<<dim3(2048 / 64, BATCH / 64), 256>>>(
            pX, 1024, Whh, HID, pG, 2048, nullptr, 0, HID, 0);
        ldot_kernel<<<BATCH / 8, 256>>>(vd);
        softmax_kernel<<<1, 1024>>>();
        ctpart_kernel<<<32, HID>>>(t);
        yfake_kernel<<<1, HID>>>(w);
        lstm_kernel<<<BATCH, HID>>>(Wih, bih, bhh);
    }

    final_kernel<<<BATCH * HID / 256, 256>>>((float*)d_out, out_size);
}

// round 7
// speedup vs baseline: 1.6236x; 1.6236x over previous
#include <cuda_runtime.h>
#include <math.h>
#include <stdint.h>
#include <mma.h>

using namespace nvcuda;

#define BATCH 2048
#define HID   512
#define WIN   24
#define LZ    514   // HID + KERNEL - 1

__device__ __forceinline__ float tf32r(float x) {   // round-to-nearest tf32
    uint32_t u; asm("cvt.rna.tf32.f32 %0, %1;" : "=r"(u) : "f"(x));
    return __uint_as_float(u);
}

// ==================== scratch (device globals; no allocations) ====================
__device__ float g_H   [(size_t)WIN * BATCH * HID];
__device__ float g_HiUd[(size_t)WIN * BATCH * HID];
__device__ float g_X   [(size_t)BATCH * 1024];
__device__ float g_L   [(size_t)BATCH * HID];
__device__ float g_G   [(size_t)BATCH * 2048];
__device__ float g_l   [BATCH];
__device__ float g_Bw  [BATCH];
__device__ float g_yr  [BATCH];
__device__ float g_yf  [BATCH];
__device__ float g_ctv [HID];
__device__ float g_part[32 * HID];

// ==================== wmma tf32 GEMM: C = [tanh](A @ B^T [+ add]) ====================
// A: [M, lda], B: [N, ldb] row-major (K contiguous). C: [M, ldc].
// CTA tile: 128 x BN, BK=32. 256 threads = 8 warps in 4(M) x 2(N).
// Warp tile: 32 x BN/2 -> 2 x (BN/32) wmma m16n16k8 fragments.
// M % 128 == 0, N % BN == 0, K % 32 == 0.
template<int BN, bool DO_ADD, bool DO_TANH>
__global__ __launch_bounds__(256) void gemm_tc(
    const float* __restrict__ A, int lda,
    const float* __restrict__ B, int ldb,
    float*       __restrict__ C, int ldc,
    const float* __restrict__ addP, int ldadd, int K)
{
    constexpr int BM = 128, BK = 32, SLD = BK + 8;     // padded smem stride
    constexpr int NFN = BN / 32;                       // n-frags per warp: 2 or 4
    constexpr int ACH = BM * BK / 4 / 256;             // 4 float4 per thread
    constexpr int BCH = BN * BK / 4 / 256;             // 2 or 4

    __shared__ float sA[BM * SLD];
    __shared__ float sB[BN * SLD];

    const int tid = threadIdx.x, wid = tid >> 5;
    const int warpM = wid & 3, warpN = wid >> 2;       // 4 x 2
    const int row0 = blockIdx.y * BM, col0 = blockIdx.x * BN;

    wmma::fragment<wmma::accumulator, 16, 16, 8, float> acc[2][NFN];
    #pragma unroll
    for (int i = 0; i < 2; i++)
        #pragma unroll
        for (int j = 0; j < NFN; j++)
            wmma::fill_fragment(acc[i][j], 0.f);

    for (int k0 = 0; k0 < K; k0 += BK) {
        #pragma unroll
        for (int i = 0; i < ACH; i++) {
            int id = tid + i * 256, r = id >> 3, c = (id & 7) * 4;
            float4 v = *(const float4*)(A + (size_t)(row0 + r) * lda + k0 + c);
            v.x = tf32r(v.x); v.y = tf32r(v.y); v.z = tf32r(v.z); v.w = tf32r(v.w);
            *(float4*)&sA[r * SLD + c] = v;
        }
        #pragma unroll
        for (int i = 0; i < BCH; i++) {
            int id = tid + i * 256, r = id >> 3, c = (id & 7) * 4;
            float4 v = *(const float4*)(B + (size_t)(col0 + r) * ldb + k0 + c);
            v.x = tf32r(v.x); v.y = tf32r(v.y); v.z = tf32r(v.z); v.w = tf32r(v.w);
            *(float4*)&sB[r * SLD + c] = v;
        }
        __syncthreads();
        #pragma unroll
        for (int kk = 0; kk < BK / 8; kk++) {
            wmma::fragment<wmma::matrix_a, 16, 16, 8, wmma::precision::tf32, wmma::row_major> af[2];
            wmma::fragment<wmma::matrix_b, 16, 16, 8, wmma::precision::tf32, wmma::col_major> bf[NFN];
            #pragma unroll
            for (int mi = 0; mi < 2; mi++)
                wmma::load_matrix_sync(af[mi], &sA[(warpM * 32 + mi * 16) * SLD + kk * 8], SLD);
            #pragma unroll
            for (int ni = 0; ni < NFN; ni++)
                wmma::load_matrix_sync(bf[ni], &sB[(warpN * (BN / 2) + ni * 16) * SLD + kk * 8], SLD);
            #pragma unroll
            for (int mi = 0; mi < 2; mi++)
                #pragma unroll
                for (int ni = 0; ni < NFN; ni++)
                    wmma::mma_sync(acc[mi][ni], af[mi], bf[ni], acc[mi][ni]);
        }
        __syncthreads();
    }

    // Epilogue: fused add (fragment-elementwise; same accumulator layout) + tanh
    #pragma unroll
    for (int mi = 0; mi < 2; mi++) {
        #pragma unroll
        for (int ni = 0; ni < NFN; ni++) {
            int r = row0 + warpM * 32 + mi * 16;
            int c = col0 + warpN * (BN / 2) + ni * 16;
            if (DO_ADD) {
                wmma::fragment<wmma::accumulator, 16, 16, 8, float> ad;
                wmma::load_matrix_sync(ad, addP + (size_t)r * ldadd + c, ldadd, wmma::mem_row_major);
                #pragma unroll
                for (int e = 0; e < acc[mi][ni].num_elements; e++)
                    acc[mi][ni].x[e] += ad.x[e];
            }
            if (DO_TANH) {
                #pragma unroll
                for (int e = 0; e < acc[mi][ni].num_elements; e++)
                    acc[mi][ni].x[e] = tanhf(acc[mi][ni].x[e]);
            }
            wmma::store_matrix_sync(C + (size_t)r * ldc + c, acc[mi][ni], ldc, wmma::mem_row_major);
        }
    }
}

// ==================== conv + relu ====================
__global__ void conv_kernel(const float* __restrict__ Z,
                            const float* __restrict__ conv_w,
                            const float* __restrict__ conv_b)
{
    int b = blockIdx.x;
    int h = threadIdx.x;
    __shared__ float z0[LZ + 2];
    __shared__ float z1[LZ + 2];
    const float* Z0 = Z + (size_t)b * LZ;
    const float* Z1 = Z + (size_t)(BATCH + b) * LZ;
    for (int i = h; i < LZ; i += HID) { z0[i] = Z0[i]; z1[i] = Z1[i]; }
    __syncthreads();
    float a0 = z0[h], a1 = z0[h + 1], a2 = z0[h + 2];
    float b0 = z1[h], b1 = z1[h + 1], b2 = z1[h + 2];
    #pragma unroll
    for (int t = 0; t < WIN; t++) {
        const float* cw = conv_w + t * 6;
        float v = conv_b[t]
                + a0 * cw[0] + a1 * cw[1] + a2 * cw[2]
                + b0 * cw[3] + b1 * cw[4] + b2 * cw[5];
        g_H[((size_t)t * BATCH + b) * HID + h] = fmaxf(v, 0.f);
    }
}

// ==================== l[b] = L[b,:] . vd ====================
__global__ void ldot_kernel(const float* __restrict__ vd)
{
    int warp = threadIdx.x >> 5, lane = threadIdx.x & 31;
    int row = blockIdx.x * 8 + warp;
    const float* lr = g_L + (size_t)row * HID;
    float s = 0.f;
    for (int j = lane; j < HID; j += 32) s = fmaf(lr[j], vd[j], s);
    #pragma unroll
    for (int o = 16; o; o >>= 1) s += __shfl_xor_sync(0xFFFFFFFFu, s, o);
    if (!lane) g_l[row] = s;
}

// ==================== softmax over batch ====================
__global__ void softmax_kernel()
{
    __shared__ float red[32];
    __shared__ float sv[2];
    int tid = threadIdx.x;
    float m = -1e30f;
    for (int i = tid; i < BATCH; i += 1024) m = fmaxf(m, g_l[i]);
    #pragma unroll
    for (int o = 16; o; o >>= 1) m = fmaxf(m, __shfl_xor_sync(0xFFFFFFFFu, m, o));
    if ((tid & 31) == 0) red[tid >> 5] = m;
    __syncthreads();
    if (tid < 32) {
        float v = red[tid];
        #pragma unroll
        for (int o = 16; o; o >>= 1) v = fmaxf(v, __shfl_xor_sync(0xFFFFFFFFu, v, o));
        if (!tid) sv[0] = v;
    }
    __syncthreads();
    m = sv[0];
    float s = 0.f;
    for (int i = tid; i < BATCH; i += 1024) s += expf(g_l[i] - m);
    #pragma unroll
    for (int o = 16; o; o >>= 1) s += __shfl_xor_sync(0xFFFFFFFFu, s, o);
    if ((tid & 31) == 0) red[tid >> 5] = s;
    __syncthreads();
    if (tid < 32) {
        float v = red[tid];
        #pragma unroll
        for (int o = 16; o; o >>= 1) v += __shfl_xor_sync(0xFFFFFFFFu, v, o);
        if (!tid) sv[1] = v;
    }
    __syncthreads();
    float inv = 1.f / sv[1];
    for (int i = tid; i < BATCH; i += 1024) g_Bw[i] = expf(g_l[i] - m) * inv;
}

// ==================== partial Bw @ H[t] ====================
__global__ void ctpart_kernel(int t)
{
    int h = threadIdx.x;
    int blk = blockIdx.x;
    const float* Ht = g_H + (size_t)t * BATCH * HID;
    float s = 0.f;
    int b0 = blk * 64;
    for (int b = b0; b < b0 + 64; b++)
        s = fmaf(g_Bw[b], Ht[(size_t)b * HID + h], s);
    g_part[blk * HID + h] = s;
}

// ==================== ctv += partials; y_fake = yr + ctv.w[24:] ====================
__global__ void yfake_kernel(const float* __restrict__ w)
{
    __shared__ float red[16];
    __shared__ float ysh;
    int h = threadIdx.x;
    float s = g_ctv[h];
    #pragma unroll
    for (int i = 0; i < 32; i++) s += g_part[i * HID + h];
    g_ctv[h] = s;
    float p = s * w[WIN + h];
    int lane = h & 31, warp = h >> 5;
    #pragma unroll
    for (int o = 16; o; o >>= 1) p += __shfl_xor_sync(0xFFFFFFFFu, p, o);
    if (!lane) red[warp] = p;
    __syncthreads();
    if (h < 32) {
        float v = (h < 16) ? red[h] : 0.f;
        #pragma unroll
        for (int o = 16; o; o >>= 1) v += __shfl_xor_sync(0xFFFFFFFFu, v, o);
        if (!h) ysh = v;
    }
    __syncthreads();
    float ys = ysh;
    for (int b = h; b < BATCH; b += HID) g_yf[b] = g_yr[b] + ys;
}

// ==================== LSTM cell update ====================
__device__ __forceinline__ float sigf(float x) { return 1.f / (1.f + expf(-x)); }

__global__ void lstm_kernel(const float* __restrict__ Wih,
                            const float* __restrict__ bih,
                            const float* __restrict__ bhh)
{
    int b = blockIdx.x, h = threadIdx.x;
    float y = g_yf[b];
    const float* g = g_G + (size_t)b * 2048;
    float ig = sigf (fmaf(y, Wih[h],           bih[h]           + bhh[h])           + g[h]);
    float fg = sigf (fmaf(y, Wih[HID + h],     bih[HID + h]     + bhh[HID + h])     + g[HID + h]);
    float gg = tanhf(fmaf(y, Wih[2*HID + h],   bih[2*HID + h]   + bhh[2*HID + h])   + g[2*HID + h]);
    float og = sigf (fmaf(y, Wih[3*HID + h],   bih[3*HID + h]   + bhh[3*HID + h])   + g[3*HID + h]);
    float* X = g_X + (size_t)b * 1024;
    float ns = fg * X[HID + h] + ig * gg;
    float nd = og * tanhf(ns);
    X[h] = nd;
    X[HID + h] = ns;
}

// ==================== init ====================
__global__ void init_kernel(const float* __restrict__ din,
                            const float* __restrict__ sin_,
                            const float* __restrict__ y_real,
                            const float* __restrict__ w,
                            const float* __restrict__ bparam)
{
    size_t i = (size_t)blockIdx.x * blockDim.x + threadIdx.x;
    int b = (int)(i / HID), h = (int)(i % HID);
    g_X[(size_t)b * 1024 + h]       = din[i];
    g_X[(size_t)b * 1024 + HID + h] = sin_[i];
    if (i < HID) g_ctv[i] = 0.f;
    if (i < BATCH) {
        float s = bparam[0];
        #pragma unroll
        for (int k = 0; k < WIN; k++) s = fmaf(y_real[i * WIN + k], w[k], s);
        g_yr[i] = s;
    }
}

// ==================== finalize ====================
__global__ void final_kernel(float* __restrict__ out, int out_size)
{
    size_t i = (size_t)blockIdx.x * blockDim.x + threadIdx.x;
    if (i < BATCH && i < (size_t)out_size) out[i] = g_yf[i];
    if (out_size >= BATCH + 2 * BATCH * HID) {
        int b = (int)(i / HID), h = (int)(i % HID);
        out[BATCH + i]               = g_X[(size_t)b * 1024 + h];
        out[BATCH + BATCH * HID + i] = g_X[(size_t)b * 1024 + HID + h];
    }
}

// ==================== launch ====================
extern "C" void kernel_launch(void* const* d_in, const int* in_sizes, int n_in,
                              void* d_out, int out_size)
{
    const float* Z      = (const float*)d_in[0];
    const float* din    = (const float*)d_in[1];
    const float* sin_   = (const float*)d_in[2];
    const float* y_real = (const float*)d_in[3];
    const float* vd     = (const float*)d_in[4];
    const float* Wd     = (const float*)d_in[5];
    const float* Ud     = (const float*)d_in[6];
    const float* w      = (const float*)d_in[7];
    const float* bparam = (const float*)d_in[8];
    const float* conv_w = (const float*)d_in[9];
    const float* conv_b = (const float*)d_in[10];
    const float* Wih    = (const float*)d_in[11];
    const float* Whh    = (const float*)d_in[12];
    const float* bih    = (const float*)d_in[13];
    const float* bhh    = (const float*)d_in[14];

    float *pH, *pHiUd, *pX, *pL, *pG;
    cudaGetSymbolAddress((void**)&pH,    g_H);
    cudaGetSymbolAddress((void**)&pHiUd, g_HiUd);
    cudaGetSymbolAddress((void**)&pX,    g_X);
    cudaGetSymbolAddress((void**)&pL,    g_L);
    cudaGetSymbolAddress((void**)&pG,    g_G);

    // Precompute: conv, HiUd = H @ Ud^T (all 24 steps as one GEMM), init
    conv_kernel<<<BATCH, HID>>>(Z, conv_w, conv_b);
    gemm_tc<128, false, false><<<dim3(HID / 128, WIN * BATCH / 128), 256>>>(
        pH, HID, Ud, HID, pHiUd, HID, nullptr, 0, HID);
    init_kernel<<<BATCH * HID / 256, 256>>>(din, sin_, y_real, w, bparam);

    for (int t = 0; t < WIN; t++) {
        // L = tanh([d0|s0] @ Wd^T + HiUd[t])   (M=2048, N=512, K=1024)
        gemm_tc<64, true, true><<<dim3(HID / 64, BATCH / 128), 256>>>(
            pX, 1024, Wd, 1024, pL, HID,
            pHiUd + (size_t)t * BATCH * HID, HID, 1024);
        // G = d0 @ Whh^T                        (M=2048, N=2048, K=512)
        gemm_tc<128, false, false><<<dim3(2048 / 128, BATCH / 128), 256>>>(
            pX, 1024, Whh, HID, pG, 2048, nullptr, 0, HID);
        ldot_kernel<<<BATCH / 8, 256>>>(vd);
        softmax_kernel<<<1, 1024>>>();
        ctpart_kernel<<<32, HID>>>(t);
        yfake_kernel<<<1, HID>>>(w);
        lstm_kernel<<<BATCH, HID>>>(Wih, bih, bhh);
    }

    final_kernel<<<BATCH * HID / 256, 256>>>((float*)d_out, out_size);
}

// round 8
// speedup vs baseline: 1.6818x; 1.0359x over previous
#include <cuda_runtime.h>
#include <math.h>
#include <stdint.h>
#include <mma.h>

using namespace nvcuda;

#define BATCH 2048
#define HID   512
#define WIN   24
#define LZ    514   // HID + KERNEL - 1

__device__ __forceinline__ float tf32r(float x) {   // round-to-nearest tf32
    uint32_t u; asm("cvt.rna.tf32.f32 %0, %1;" : "=r"(u) : "f"(x));
    return __uint_as_float(u);
}

// ==================== scratch (device globals; no allocations) ====================
__device__ float g_H   [(size_t)WIN * BATCH * HID];
__device__ float g_HiUd[(size_t)WIN * BATCH * HID];
__device__ float g_X   [(size_t)BATCH * 1024];
__device__ float g_L   [(size_t)BATCH * HID];
__device__ float g_G   [(size_t)BATCH * 2048];
__device__ float g_l   [BATCH];
__device__ float g_Bw  [BATCH];
__device__ float g_yr  [BATCH];
__device__ float g_yf  [BATCH];
__device__ float g_ctv [HID];
__device__ float g_part[32 * HID];
__device__ unsigned int g_cnt;

// ==================== shared GEMM body: C = [tanh](A @ B^T [+ add]) ====================
// Tile 128x128, BK=32, 256 threads (8 warps, 4M x 2N, warp tile 32x64 = 2x4 frags).
// Double-buffered smem + register prefetch: one __syncthreads per K-chunk.
// Dynamic smem: 4 buffers of 128*36 floats = 73728 bytes.
#define SLD   36
#define BUFSZ (128 * SLD)          // 4608 floats
#define GEMM_SMEM_BYTES (4 * BUFSZ * 4)

__device__ __forceinline__ void gemm_body(
    const float* __restrict__ A, int lda,
    const float* __restrict__ B, int ldb,
    float*       __restrict__ C, int ldc,
    const float* __restrict__ addP, int ldadd,
    int K, bool do_tanh, int row0, int col0, float* smem)
{
    const int tid = threadIdx.x, wid = tid >> 5;
    const int warpM = wid & 3, warpN = wid >> 2;          // 4 x 2
    const int rb_ = tid >> 3;                              // 0..31
    const int cb_ = (tid & 7) * 4;                         // 0..28

    const float* Aptr = A + (size_t)(row0 + rb_) * lda + cb_;
    const float* Bptr = B + (size_t)(col0 + rb_) * ldb + cb_;

    wmma::fragment<wmma::accumulator, 16, 16, 8, float> acc[2][4];
    #pragma unroll
    for (int mi = 0; mi < 2; mi++)
        #pragma unroll
        for (int ni = 0; ni < 4; ni++)
            wmma::fill_fragment(acc[mi][ni], 0.f);

    float4 ra[4], rb4[4];

    // prologue: load + store chunk 0
    #pragma unroll
    for (int i = 0; i < 4; i++) {
        ra[i]  = *(const float4*)(Aptr + (size_t)(i * 32) * lda);
        rb4[i] = *(const float4*)(Bptr + (size_t)(i * 32) * ldb);
    }
    {
        float* sA = smem;
        float* sB = smem + 2 * BUFSZ;
        #pragma unroll
        for (int i = 0; i < 4; i++) {
            float4 v = ra[i];
            v.x = tf32r(v.x); v.y = tf32r(v.y); v.z = tf32r(v.z); v.w = tf32r(v.w);
            *(float4*)&sA[(rb_ + i * 32) * SLD + cb_] = v;
            float4 u = rb4[i];
            u.x = tf32r(u.x); u.y = tf32r(u.y); u.z = tf32r(u.z); u.w = tf32r(u.w);
            *(float4*)&sB[(rb_ + i * 32) * SLD + cb_] = u;
        }
    }
    __syncthreads();

    const int nk = K >> 5;
    for (int kc = 0; kc < nk; kc++) {
        const int cur = kc & 1;
        const bool more = (kc + 1 < nk);
        if (more) {
            const int k0 = (kc + 1) << 5;
            #pragma unroll
            for (int i = 0; i < 4; i++) {
                ra[i]  = *(const float4*)(Aptr + (size_t)(i * 32) * lda + k0);
                rb4[i] = *(const float4*)(Bptr + (size_t)(i * 32) * ldb + k0);
            }
        }
        const float* sA = smem + cur * BUFSZ;
        const float* sB = smem + 2 * BUFSZ + cur * BUFSZ;
        #pragma unroll
        for (int kk = 0; kk < 4; kk++) {
            wmma::fragment<wmma::matrix_a, 16, 16, 8, wmma::precision::tf32, wmma::row_major> af[2];
            wmma::fragment<wmma::matrix_b, 16, 16, 8, wmma::precision::tf32, wmma::col_major> bf[4];
            #pragma unroll
            for (int mi = 0; mi < 2; mi++)
                wmma::load_matrix_sync(af[mi], &sA[(warpM * 32 + mi * 16) * SLD + kk * 8], SLD);
            #pragma unroll
            for (int ni = 0; ni < 4; ni++)
                wmma::load_matrix_sync(bf[ni], &sB[(warpN * 64 + ni * 16) * SLD + kk * 8], SLD);
            #pragma unroll
            for (int mi = 0; mi < 2; mi++)
                #pragma unroll
                for (int ni = 0; ni < 4; ni++)
                    wmma::mma_sync(acc[mi][ni], af[mi], bf[ni], acc[mi][ni]);
        }
        if (more) {
            float* dA = smem + (cur ^ 1) * BUFSZ;
            float* dB = smem + 2 * BUFSZ + (cur ^ 1) * BUFSZ;
            #pragma unroll
            for (int i = 0; i < 4; i++) {
                float4 v = ra[i];
                v.x = tf32r(v.x); v.y = tf32r(v.y); v.z = tf32r(v.z); v.w = tf32r(v.w);
                *(float4*)&dA[(rb_ + i * 32) * SLD + cb_] = v;
                float4 u = rb4[i];
                u.x = tf32r(u.x); u.y = tf32r(u.y); u.z = tf32r(u.z); u.w = tf32r(u.w);
                *(float4*)&dB[(rb_ + i * 32) * SLD + cb_] = u;
            }
        }
        __syncthreads();
    }

    // epilogue: fused add (accumulator-layout elementwise) + tanh
    #pragma unroll
    for (int mi = 0; mi < 2; mi++) {
        #pragma unroll
        for (int ni = 0; ni < 4; ni++) {
            int rr = row0 + warpM * 32 + mi * 16;
            int cc = col0 + warpN * 64 + ni * 16;
            if (addP) {
                wmma::fragment<wmma::accumulator, 16, 16, 8, float> ad;
                wmma::load_matrix_sync(ad, addP + (size_t)rr * ldadd + cc, ldadd, wmma::mem_row_major);
                #pragma unroll
                for (int e = 0; e < acc[mi][ni].num_elements; e++)
                    acc[mi][ni].x[e] += ad.x[e];
            }
            if (do_tanh) {
                #pragma unroll
                for (int e = 0; e < acc[mi][ni].num_elements; e++)
                    acc[mi][ni].x[e] = tanhf(acc[mi][ni].x[e]);
            }
            wmma::store_matrix_sync(C + (size_t)rr * ldc + cc, acc[mi][ni], ldc, wmma::mem_row_major);
        }
    }
}

// ---- fused per-step GEMM: blocks 0..63 = L-gemm, 64..319 = G-gemm ----
__global__ __launch_bounds__(256) void step_gemm(
    const float* __restrict__ X,
    const float* __restrict__ Wd,
    const float* __restrict__ Whh,
    const float* __restrict__ HiUd_t)
{
    extern __shared__ float smem[];
    int id = blockIdx.x;
    if (id < 64) {
        int bx = id & 3, by = id >> 2;       // N=512/128=4, M=2048/128=16
        gemm_body(X, 1024, Wd, 1024, g_L, 512, HiUd_t, 512,
                  1024, true, by * 128, bx * 128, smem);
    } else {
        id -= 64;
        int bx = id & 15, by = id >> 4;      // N=2048/128=16, M=16
        gemm_body(X, 1024, Whh, 512, g_G, 2048, nullptr, 0,
                  512, false, by * 128, bx * 128, smem);
    }
}

// ---- precompute GEMM: HiUd = H @ Ud^T ----
__global__ __launch_bounds__(256) void gemm_pre(
    const float* __restrict__ Ud)
{
    extern __shared__ float smem[];
    gemm_body(g_H, 512, Ud, 512, g_HiUd, 512, nullptr, 0,
              512, false, blockIdx.y * 128, blockIdx.x * 128, smem);
}

// ==================== conv + relu ====================
__global__ void conv_kernel(const float* __restrict__ Z,
                            const float* __restrict__ conv_w,
                            const float* __restrict__ conv_b)
{
    int b = blockIdx.x;
    int h = threadIdx.x;
    __shared__ float z0[LZ + 2];
    __shared__ float z1[LZ + 2];
    const float* Z0 = Z + (size_t)b * LZ;
    const float* Z1 = Z + (size_t)(BATCH + b) * LZ;
    for (int i = h; i < LZ; i += HID) { z0[i] = Z0[i]; z1[i] = Z1[i]; }
    __syncthreads();
    float a0 = z0[h], a1 = z0[h + 1], a2 = z0[h + 2];
    float b0 = z1[h], b1 = z1[h + 1], b2 = z1[h + 2];
    #pragma unroll
    for (int t = 0; t < WIN; t++) {
        const float* cw = conv_w + t * 6;
        float v = conv_b[t]
                + a0 * cw[0] + a1 * cw[1] + a2 * cw[2]
                + b0 * cw[3] + b1 * cw[4] + b2 * cw[5];
        g_H[((size_t)t * BATCH + b) * HID + h] = fmaxf(v, 0.f);
    }
}

// ==================== l[b] = L[b,:] . vd ====================
__global__ void ldot_kernel(const float* __restrict__ vd)
{
    int warp = threadIdx.x >> 5, lane = threadIdx.x & 31;
    int row = blockIdx.x * 8 + warp;
    const float* lr = g_L + (size_t)row * HID;
    float s = 0.f;
    for (int j = lane; j < HID; j += 32) s = fmaf(lr[j], vd[j], s);
    #pragma unroll
    for (int o = 16; o; o >>= 1) s += __shfl_xor_sync(0xFFFFFFFFu, s, o);
    if (!lane) g_l[row] = s;
}

// ==================== softmax over batch ====================
__global__ void softmax_kernel()
{
    __shared__ float red[32];
    __shared__ float sv[2];
    int tid = threadIdx.x;
    float m = -1e30f;
    for (int i = tid; i < BATCH; i += 1024) m = fmaxf(m, g_l[i]);
    #pragma unroll
    for (int o = 16; o; o >>= 1) m = fmaxf(m, __shfl_xor_sync(0xFFFFFFFFu, m, o));
    if ((tid & 31) == 0) red[tid >> 5] = m;
    __syncthreads();
    if (tid < 32) {
        float v = red[tid];
        #pragma unroll
        for (int o = 16; o; o >>= 1) v = fmaxf(v, __shfl_xor_sync(0xFFFFFFFFu, v, o));
        if (!tid) sv[0] = v;
    }
    __syncthreads();
    m = sv[0];
    float s = 0.f;
    for (int i = tid; i < BATCH; i += 1024) s += expf(g_l[i] - m);
    #pragma unroll
    for (int o = 16; o; o >>= 1) s += __shfl_xor_sync(0xFFFFFFFFu, s, o);
    if ((tid & 31) == 0) red[tid >> 5] = s;
    __syncthreads();
    if (tid < 32) {
        float v = red[tid];
        #pragma unroll
        for (int o = 16; o; o >>= 1) v += __shfl_xor_sync(0xFFFFFFFFu, v, o);
        if (!tid) sv[1] = v;
    }
    __syncthreads();
    float inv = 1.f / sv[1];
    for (int i = tid; i < BATCH; i += 1024) g_Bw[i] = expf(g_l[i] - m) * inv;
}

// ==================== fused: partial Bw@H[t] (32 blocks) + last-block yfake ====================
__global__ void ctpart_yfake_kernel(int t, const float* __restrict__ w)
{
    int h = threadIdx.x;                   // 512 threads
    int blk = blockIdx.x;                  // 32 blocks
    const float* Ht = g_H + (size_t)t * BATCH * HID;
    float s = 0.f;
    int b0 = blk * 64;
    for (int b = b0; b < b0 + 64; b++)
        s = fmaf(g_Bw[b], Ht[(size_t)b * HID + h], s);
    g_part[blk * HID + h] = s;
    __threadfence();

    __shared__ bool last;
    if (h == 0) {
        unsigned v = atomicAdd(&g_cnt, 1u);
        last = (v == 31u);
    }
    __syncthreads();
    if (!last) return;
    if (h == 0) g_cnt = 0u;

    // ---- yfake body (single block; fixed-order sums -> deterministic) ----
    __shared__ float red[16];
    __shared__ float ysh;
    float acc = g_ctv[h];
    #pragma unroll
    for (int i = 0; i < 32; i++) acc += g_part[i * HID + h];
    g_ctv[h] = acc;
    float p = acc * w[WIN + h];
    int lane = h & 31, warp = h >> 5;
    #pragma unroll
    for (int o = 16; o; o >>= 1) p += __shfl_xor_sync(0xFFFFFFFFu, p, o);
    if (!lane) red[warp] = p;
    __syncthreads();
    if (h < 32) {
        float v = (h < 16) ? red[h] : 0.f;
        #pragma unroll
        for (int o = 16; o; o >>= 1) v += __shfl_xor_sync(0xFFFFFFFFu, v, o);
        if (!h) ysh = v;
    }
    __syncthreads();
    float ys = ysh;
    for (int b = h; b < BATCH; b += HID) g_yf[b] = g_yr[b] + ys;
}

// ==================== LSTM cell update ====================
__device__ __forceinline__ float sigf(float x) { return 1.f / (1.f + expf(-x)); }

__global__ void lstm_kernel(const float* __restrict__ Wih,
                            const float* __restrict__ bih,
                            const float* __restrict__ bhh)
{
    int b = blockIdx.x, h = threadIdx.x;
    float y = g_yf[b];
    const float* g = g_G + (size_t)b * 2048;
    float ig = sigf (fmaf(y, Wih[h],           bih[h]           + bhh[h])           + g[h]);
    float fg = sigf (fmaf(y, Wih[HID + h],     bih[HID + h]     + bhh[HID + h])     + g[HID + h]);
    float gg = tanhf(fmaf(y, Wih[2*HID + h],   bih[2*HID + h]   + bhh[2*HID + h])   + g[2*HID + h]);
    float og = sigf (fmaf(y, Wih[3*HID + h],   bih[3*HID + h]   + bhh[3*HID + h])   + g[3*HID + h]);
    float* X = g_X + (size_t)b * 1024;
    float ns = fg * X[HID + h] + ig * gg;
    float nd = og * tanhf(ns);
    X[h] = nd;
    X[HID + h] = ns;
}

// ==================== init ====================
__global__ void init_kernel(const float* __restrict__ din,
                            const float* __restrict__ sin_,
                            const float* __restrict__ y_real,
                            const float* __restrict__ w,
                            const float* __restrict__ bparam)
{
    size_t i = (size_t)blockIdx.x * blockDim.x + threadIdx.x;
    int b = (int)(i / HID), h = (int)(i % HID);
    g_X[(size_t)b * 1024 + h]       = din[i];
    g_X[(size_t)b * 1024 + HID + h] = sin_[i];
    if (i < HID) g_ctv[i] = 0.f;
    if (i == 0)  g_cnt = 0u;
    if (i < BATCH) {
        float s = bparam[0];
        #pragma unroll
        for (int k = 0; k < WIN; k++) s = fmaf(y_real[i * WIN + k], w[k], s);
        g_yr[i] = s;
    }
}

// ==================== finalize ====================
__global__ void final_kernel(float* __restrict__ out, int out_size)
{
    size_t i = (size_t)blockIdx.x * blockDim.x + threadIdx.x;
    if (i < BATCH && i < (size_t)out_size) out[i] = g_yf[i];
    if (out_size >= BATCH + 2 * BATCH * HID) {
        int b = (int)(i / HID), h = (int)(i % HID);
        out[BATCH + i]               = g_X[(size_t)b * 1024 + h];
        out[BATCH + BATCH * HID + i] = g_X[(size_t)b * 1024 + HID + h];
    }
}

// ==================== launch ====================
extern "C" void kernel_launch(void* const* d_in, const int* in_sizes, int n_in,
                              void* d_out, int out_size)
{
    const float* Z      = (const float*)d_in[0];
    const float* din    = (const float*)d_in[1];
    const float* sin_   = (const float*)d_in[2];
    const float* y_real = (const float*)d_in[3];
    const float* vd     = (const float*)d_in[4];
    const float* Wd     = (const float*)d_in[5];
    const float* Ud     = (const float*)d_in[6];
    const float* w      = (const float*)d_in[7];
    const float* bparam = (const float*)d_in[8];
    const float* conv_w = (const float*)d_in[9];
    const float* conv_b = (const float*)d_in[10];
    const float* Wih    = (const float*)d_in[11];
    const float* Whh    = (const float*)d_in[12];
    const float* bih    = (const float*)d_in[13];
    const float* bhh    = (const float*)d_in[14];

    float *pX, *pHiUd;
    cudaGetSymbolAddress((void**)&pX,    g_X);
    cudaGetSymbolAddress((void**)&pHiUd, g_HiUd);

    cudaFuncSetAttribute(step_gemm, cudaFuncAttributeMaxDynamicSharedMemorySize, GEMM_SMEM_BYTES);
    cudaFuncSetAttribute(gemm_pre,  cudaFuncAttributeMaxDynamicSharedMemorySize, GEMM_SMEM_BYTES);

    // Precompute: conv, HiUd = H @ Ud^T (all 24 steps as one GEMM), init
    conv_kernel<<<BATCH, HID>>>(Z, conv_w, conv_b);
    gemm_pre<<<dim3(HID / 128, WIN * BATCH / 128), 256, GEMM_SMEM_BYTES>>>(Ud);
    init_kernel<<<BATCH * HID / 256, 256>>>(din, sin_, y_real, w, bparam);

    for (int t = 0; t < WIN; t++) {
        step_gemm<<<320, 256, GEMM_SMEM_BYTES>>>(
            pX, Wd, Whh, pHiUd + (size_t)t * BATCH * HID);
        ldot_kernel<<<BATCH / 8, 256>>>(vd);
        softmax_kernel<<<1, 1024>>>();
        ctpart_yfake_kernel<<<32, HID>>>(t, w);
        lstm_kernel<<<BATCH, HID>>>(Wih, bih, bhh);
    }

    final_kernel<<<BATCH * HID / 256, 256>>>((float*)d_out, out_size);
}

// round 9
// speedup vs baseline: 1.7792x; 1.0579x over previous
#include <cuda_runtime.h>
#include <math.h>
#include <stdint.h>
#include <mma.h>

using namespace nvcuda;

#define BATCH 2048
#define HID   512
#define WIN   24
#define LZ    514   // HID + KERNEL - 1

__device__ __forceinline__ float tf32r(float x) {   // round-to-nearest tf32
    uint32_t u; asm("cvt.rna.tf32.f32 %0, %1;" : "=r"(u) : "f"(x));
    return __uint_as_float(u);
}

// ==================== scratch (device globals; no allocations) ====================
__device__ float g_H   [(size_t)WIN * BATCH * HID];
__device__ float g_HiUd[(size_t)WIN * BATCH * HID];
__device__ float g_X   [(size_t)BATCH * 1024];
__device__ float g_G   [(size_t)BATCH * 2048];
__device__ float g_lp  [4 * BATCH];                  // per-coltile partial tanh-dots
__device__ float g_yr  [BATCH];
__device__ float g_yf  [BATCH];
__device__ float g_ctv [HID];
__device__ float g_part[32 * HID];
__device__ unsigned int g_cnt;

// ==================== GEMM body: 128x128 tile, BK=32, 512 threads (16 warps 4x4) ====================
// Warp tile 32x32 -> 2x2 m16n16k8 tf32 frags. Double-buffered smem, reg prefetch.
// MODE 0: C = A@B^T (store to C).
// MODE 1: T = A@B^T + add; write per-row partials lp[row] = sum_c tanh(T[row,c])*vd[col0+c].
#define SLD   36
#define BUFSZ (128 * SLD)                 // 4608 floats per buffer
#define SLT   132                         // epilogue tile stride
#define GEMM_SMEM_BYTES (4 * BUFSZ * 4)   // 73728 bytes (also >= 128*SLT*4)

template<int MODE>
__device__ __forceinline__ void gemm_body512(
    const float* __restrict__ A, int lda,
    const float* __restrict__ B, int ldb,
    float*       __restrict__ C, int ldc,
    const float* __restrict__ addP, int ldadd,
    const float* __restrict__ vd, float* __restrict__ lpOut,
    int K, int row0, int col0, float* smem)
{
    const int tid = threadIdx.x, wid = tid >> 5, lane = tid & 31;
    const int warpM = wid & 3, warpN = wid >> 2;           // 4 x 4
    const int rb_ = tid >> 3;                              // 0..63
    const int cb_ = (tid & 7) * 4;                         // 0,4,..,28

    const float* Aptr = A + (size_t)(row0 + rb_) * lda + cb_;
    const float* Bptr = B + (size_t)(col0 + rb_) * ldb + cb_;

    wmma::fragment<wmma::accumulator, 16, 16, 8, float> acc[2][2];
    #pragma unroll
    for (int mi = 0; mi < 2; mi++)
        #pragma unroll
        for (int ni = 0; ni < 2; ni++)
            wmma::fill_fragment(acc[mi][ni], 0.f);

    float4 ra[2], rb4[2];
    #pragma unroll
    for (int i = 0; i < 2; i++) {
        ra[i]  = *(const float4*)(Aptr + (size_t)(i * 64) * lda);
        rb4[i] = *(const float4*)(Bptr + (size_t)(i * 64) * ldb);
    }
    {
        float* sA = smem;
        float* sB = smem + 2 * BUFSZ;
        #pragma unroll
        for (int i = 0; i < 2; i++) {
            float4 v = ra[i];
            v.x = tf32r(v.x); v.y = tf32r(v.y); v.z = tf32r(v.z); v.w = tf32r(v.w);
            *(float4*)&sA[(rb_ + i * 64) * SLD + cb_] = v;
            float4 u = rb4[i];
            u.x = tf32r(u.x); u.y = tf32r(u.y); u.z = tf32r(u.z); u.w = tf32r(u.w);
            *(float4*)&sB[(rb_ + i * 64) * SLD + cb_] = u;
        }
    }
    __syncthreads();

    const int nk = K >> 5;
    for (int kc = 0; kc < nk; kc++) {
        const int cur = kc & 1;
        const bool more = (kc + 1 < nk);
        if (more) {
            const int k0 = (kc + 1) << 5;
            #pragma unroll
            for (int i = 0; i < 2; i++) {
                ra[i]  = *(const float4*)(Aptr + (size_t)(i * 64) * lda + k0);
                rb4[i] = *(const float4*)(Bptr + (size_t)(i * 64) * ldb + k0);
            }
        }
        const float* sA = smem + cur * BUFSZ;
        const float* sB = smem + 2 * BUFSZ + cur * BUFSZ;
        #pragma unroll
        for (int kk = 0; kk < 4; kk++) {
            wmma::fragment<wmma::matrix_a, 16, 16, 8, wmma::precision::tf32, wmma::row_major> af[2];
            wmma::fragment<wmma::matrix_b, 16, 16, 8, wmma::precision::tf32, wmma::col_major> bf[2];
            #pragma unroll
            for (int mi = 0; mi < 2; mi++)
                wmma::load_matrix_sync(af[mi], &sA[(warpM * 32 + mi * 16) * SLD + kk * 8], SLD);
            #pragma unroll
            for (int ni = 0; ni < 2; ni++)
                wmma::load_matrix_sync(bf[ni], &sB[(warpN * 32 + ni * 16) * SLD + kk * 8], SLD);
            #pragma unroll
            for (int mi = 0; mi < 2; mi++)
                #pragma unroll
                for (int ni = 0; ni < 2; ni++)
                    wmma::mma_sync(acc[mi][ni], af[mi], bf[ni], acc[mi][ni]);
        }
        if (more) {
            float* dA = smem + (cur ^ 1) * BUFSZ;
            float* dB = smem + 2 * BUFSZ + (cur ^ 1) * BUFSZ;
            #pragma unroll
            for (int i = 0; i < 2; i++) {
                float4 v = ra[i];
                v.x = tf32r(v.x); v.y = tf32r(v.y); v.z = tf32r(v.z); v.w = tf32r(v.w);
                *(float4*)&dA[(rb_ + i * 64) * SLD + cb_] = v;
                float4 u = rb4[i];
                u.x = tf32r(u.x); u.y = tf32r(u.y); u.z = tf32r(u.z); u.w = tf32r(u.w);
                *(float4*)&dB[(rb_ + i * 64) * SLD + cb_] = u;
            }
        }
        __syncthreads();
    }

    if (MODE == 0) {
        #pragma unroll
        for (int mi = 0; mi < 2; mi++)
            #pragma unroll
            for (int ni = 0; ni < 2; ni++)
                wmma::store_matrix_sync(
                    C + (size_t)(row0 + warpM * 32 + mi * 16) * ldc
                      + col0 + warpN * 32 + ni * 16,
                    acc[mi][ni], ldc, wmma::mem_row_major);
    } else {
        // add HiUd, spill tile to smem, then per-row tanh-dot with vd
        #pragma unroll
        for (int mi = 0; mi < 2; mi++) {
            #pragma unroll
            for (int ni = 0; ni < 2; ni++) {
                int rr = row0 + warpM * 32 + mi * 16;
                int cc = col0 + warpN * 32 + ni * 16;
                wmma::fragment<wmma::accumulator, 16, 16, 8, float> ad;
                wmma::load_matrix_sync(ad, addP + (size_t)rr * ldadd + cc, ldadd, wmma::mem_row_major);
                #pragma unroll
                for (int e = 0; e < acc[mi][ni].num_elements; e++)
                    acc[mi][ni].x[e] += ad.x[e];
                wmma::store_matrix_sync(
                    &smem[(warpM * 32 + mi * 16) * SLT + warpN * 32 + ni * 16],
                    acc[mi][ni], SLT, wmma::mem_row_major);
            }
        }
        __syncthreads();
        float4 vdv = *(const float4*)(vd + col0 + lane * 4);
        #pragma unroll
        for (int r8 = 0; r8 < 8; r8++) {
            int row = wid * 8 + r8;
            float4 v = *(const float4*)&smem[row * SLT + lane * 4];
            float s = tanhf(v.x) * vdv.x + tanhf(v.y) * vdv.y
                    + tanhf(v.z) * vdv.z + tanhf(v.w) * vdv.w;
            #pragma unroll
            for (int o = 16; o; o >>= 1) s += __shfl_xor_sync(0xFFFFFFFFu, s, o);
            if (!lane) lpOut[row0 + row] = s;
        }
    }
}

// ---- fused per-step GEMM: blocks 0..63 = L-gemm (dot mode), 64..319 = G-gemm ----
__global__ __launch_bounds__(512) void step_gemm(
    const float* __restrict__ X,
    const float* __restrict__ Wd,
    const float* __restrict__ Whh,
    const float* __restrict__ HiUd_t,
    const float* __restrict__ vd)
{
    extern __shared__ float smem[];
    int id = blockIdx.x;
    if (id < 64) {
        int bx = id & 3, by = id >> 2;       // 4 col-tiles x 16 row-tiles
        gemm_body512<1>(X, 1024, Wd, 1024, nullptr, 0, HiUd_t, 512,
                        vd, g_lp + bx * BATCH, 1024, by * 128, bx * 128, smem);
    } else {
        id -= 64;
        int bx = id & 15, by = id >> 4;      // 16 x 16
        gemm_body512<0>(X, 1024, Whh, 512, g_G, 2048, nullptr, 0,
                        nullptr, nullptr, 512, by * 128, bx * 128, smem);
    }
}

// ---- precompute GEMM: HiUd = H @ Ud^T ----
__global__ __launch_bounds__(512) void gemm_pre(const float* __restrict__ Ud)
{
    extern __shared__ float smem[];
    gemm_body512<0>(g_H, 512, Ud, 512, g_HiUd, 512, nullptr, 0,
                    nullptr, nullptr, 512, blockIdx.y * 128, blockIdx.x * 128, smem);
}

// ==================== conv + relu ====================
__global__ void conv_kernel(const float* __restrict__ Z,
                            const float* __restrict__ conv_w,
                            const float* __restrict__ conv_b)
{
    int b = blockIdx.x;
    int h = threadIdx.x;
    __shared__ float z0[LZ + 2];
    __shared__ float z1[LZ + 2];
    const float* Z0 = Z + (size_t)b * LZ;
    const float* Z1 = Z + (size_t)(BATCH + b) * LZ;
    for (int i = h; i < LZ; i += HID) { z0[i] = Z0[i]; z1[i] = Z1[i]; }
    __syncthreads();
    float a0 = z0[h], a1 = z0[h + 1], a2 = z0[h + 2];
    float b0 = z1[h], b1 = z1[h + 1], b2 = z1[h + 2];
    #pragma unroll
    for (int t = 0; t < WIN; t++) {
        const float* cw = conv_w + t * 6;
        float v = conv_b[t]
                + a0 * cw[0] + a1 * cw[1] + a2 * cw[2]
                + b0 * cw[3] + b1 * cw[4] + b2 * cw[5];
        g_H[((size_t)t * BATCH + b) * HID + h] = fmaxf(v, 0.f);
    }
}

// ==================== fused: softmax(l) + partial Bw@H[t] + last-block yfake ====================
// grid 32 x 512 threads. Each block redundantly computes softmax stats from g_lp.
__global__ void smax_ct_yfake_kernel(int t, const float* __restrict__ w)
{
    __shared__ float sl[BATCH];          // 8 KB
    __shared__ float red[16];
    __shared__ float sv[2];
    const int tid = threadIdx.x;         // 512
    const int wid = tid >> 5, lane = tid & 31;

    for (int i = tid; i < BATCH; i += 512)
        sl[i] = g_lp[i] + g_lp[BATCH + i] + g_lp[2 * BATCH + i] + g_lp[3 * BATCH + i];
    __syncthreads();

    // max
    float m = -1e30f;
    for (int i = tid; i < BATCH; i += 512) m = fmaxf(m, sl[i]);
    #pragma unroll
    for (int o = 16; o; o >>= 1) m = fmaxf(m, __shfl_xor_sync(0xFFFFFFFFu, m, o));
    if (!lane) red[wid] = m;
    __syncthreads();
    if (tid < 32) {
        float v = (tid < 16) ? red[tid] : -1e30f;
        #pragma unroll
        for (int o = 16; o; o >>= 1) v = fmaxf(v, __shfl_xor_sync(0xFFFFFFFFu, v, o));
        if (!tid) sv[0] = v;
    }
    __syncthreads();
    m = sv[0];
    // sum of exp
    float s = 0.f;
    for (int i = tid; i < BATCH; i += 512) s += expf(sl[i] - m);
    #pragma unroll
    for (int o = 16; o; o >>= 1) s += __shfl_xor_sync(0xFFFFFFFFu, s, o);
    if (!lane) red[wid] = s;
    __syncthreads();
    if (tid < 32) {
        float v = (tid < 16) ? red[tid] : 0.f;
        #pragma unroll
        for (int o = 16; o; o >>= 1) v += __shfl_xor_sync(0xFFFFFFFFu, v, o);
        if (!tid) sv[1] = v;
    }
    __syncthreads();
    const float inv = 1.f / sv[1];

    // ctpart: this block's 64 batch rows, all 512 h (fixed order -> deterministic)
    const int h = tid, blk = blockIdx.x;
    const float* Ht = g_H + (size_t)t * BATCH * HID;
    float acc = 0.f;
    const int b0 = blk * 64;
    for (int b = b0; b < b0 + 64; b++)
        acc = fmaf(expf(sl[b] - m) * inv, Ht[(size_t)b * HID + h], acc);
    g_part[blk * HID + h] = acc;
    __threadfence();

    __shared__ bool last;
    if (h == 0) {
        unsigned v = atomicAdd(&g_cnt, 1u);
        last = (v == 31u);
    }
    __syncthreads();
    if (!last) return;
    if (h == 0) g_cnt = 0u;

    // yfake: ctv += partials; ys = ctv . w[24:]; y_fake = yr + ys
    __shared__ float ysh;
    float cv = g_ctv[h];
    #pragma unroll
    for (int i = 0; i < 32; i++) cv += g_part[i * HID + h];
    g_ctv[h] = cv;
    float p = cv * w[WIN + h];
    #pragma unroll
    for (int o = 16; o; o >>= 1) p += __shfl_xor_sync(0xFFFFFFFFu, p, o);
    if (!lane) red[wid] = p;
    __syncthreads();
    if (tid < 32) {
        float v = (tid < 16) ? red[tid] : 0.f;
        #pragma unroll
        for (int o = 16; o; o >>= 1) v += __shfl_xor_sync(0xFFFFFFFFu, v, o);
        if (!tid) ysh = v;
    }
    __syncthreads();
    const float ys = ysh;
    for (int b = h; b < BATCH; b += 512) g_yf[b] = g_yr[b] + ys;
}

// ==================== LSTM cell update ====================
__device__ __forceinline__ float sigf(float x) { return 1.f / (1.f + expf(-x)); }

__global__ void lstm_kernel(const float* __restrict__ Wih,
                            const float* __restrict__ bih,
                            const float* __restrict__ bhh)
{
    int b = blockIdx.x, h = threadIdx.x;
    float y = g_yf[b];
    const float* g = g_G + (size_t)b * 2048;
    float ig = sigf (fmaf(y, Wih[h],           bih[h]           + bhh[h])           + g[h]);
    float fg = sigf (fmaf(y, Wih[HID + h],     bih[HID + h]     + bhh[HID + h])     + g[HID + h]);
    float gg = tanhf(fmaf(y, Wih[2*HID + h],   bih[2*HID + h]   + bhh[2*HID + h])   + g[2*HID + h]);
    float og = sigf (fmaf(y, Wih[3*HID + h],   bih[3*HID + h]   + bhh[3*HID + h])   + g[3*HID + h]);
    float* X = g_X + (size_t)b * 1024;
    float ns = fg * X[HID + h] + ig * gg;
    float nd = og * tanhf(ns);
    X[h] = nd;
    X[HID + h] = ns;
}

// ==================== init ====================
__global__ void init_kernel(const float* __restrict__ din,
                            const float* __restrict__ sin_,
                            const float* __restrict__ y_real,
                            const float* __restrict__ w,
                            const float* __restrict__ bparam)
{
    size_t i = (size_t)blockIdx.x * blockDim.x + threadIdx.x;
    int b = (int)(i / HID), h = (int)(i % HID);
    g_X[(size_t)b * 1024 + h]       = din[i];
    g_X[(size_t)b * 1024 + HID + h] = sin_[i];
    if (i < HID) g_ctv[i] = 0.f;
    if (i == 0)  g_cnt = 0u;
    if (i < BATCH) {
        float s = bparam[0];
        #pragma unroll
        for (int k = 0; k < WIN; k++) s = fmaf(y_real[i * WIN + k], w[k], s);
        g_yr[i] = s;
    }
}

// ==================== finalize ====================
__global__ void final_kernel(float* __restrict__ out, int out_size)
{
    size_t i = (size_t)blockIdx.x * blockDim.x + threadIdx.x;
    if (i < BATCH && i < (size_t)out_size) out[i] = g_yf[i];
    if (out_size >= BATCH + 2 * BATCH * HID) {
        int b = (int)(i / HID), h = (int)(i % HID);
        out[BATCH + i]               = g_X[(size_t)b * 1024 + h];
        out[BATCH + BATCH * HID + i] = g_X[(size_t)b * 1024 + HID + h];
    }
}

// ==================== launch ====================
extern "C" void kernel_launch(void* const* d_in, const int* in_sizes, int n_in,
                              void* d_out, int out_size)
{
    const float* Z      = (const float*)d_in[0];
    const float* din    = (const float*)d_in[1];
    const float* sin_   = (const float*)d_in[2];
    const float* y_real = (const float*)d_in[3];
    const float* vd     = (const float*)d_in[4];
    const float* Wd     = (const float*)d_in[5];
    const float* Ud     = (const float*)d_in[6];
    const float* w      = (const float*)d_in[7];
    const float* bparam = (const float*)d_in[8];
    const float* conv_w = (const float*)d_in[9];
    const float* conv_b = (const float*)d_in[10];
    const float* Wih    = (const float*)d_in[11];
    const float* Whh    = (const float*)d_in[12];
    const float* bih    = (const float*)d_in[13];
    const float* bhh    = (const float*)d_in[14];

    float *pX, *pHiUd;
    cudaGetSymbolAddress((void**)&pX,    g_X);
    cudaGetSymbolAddress((void**)&pHiUd, g_HiUd);

    cudaFuncSetAttribute(step_gemm, cudaFuncAttributeMaxDynamicSharedMemorySize, GEMM_SMEM_BYTES);
    cudaFuncSetAttribute(gemm_pre,  cudaFuncAttributeMaxDynamicSharedMemorySize, GEMM_SMEM_BYTES);

    conv_kernel<<<BATCH, HID>>>(Z, conv_w, conv_b);
    gemm_pre<<<dim3(HID / 128, WIN * BATCH / 128), 512, GEMM_SMEM_BYTES>>>(Ud);
    init_kernel<<<BATCH * HID / 256, 256>>>(din, sin_, y_real, w, bparam);

    for (int t = 0; t < WIN; t++) {
        step_gemm<<<320, 512, GEMM_SMEM_BYTES>>>(
            pX, Wd, Whh, pHiUd + (size_t)t * BATCH * HID, vd);
        smax_ct_yfake_kernel<<<32, HID>>>(t, w);
        lstm_kernel<<<BATCH, HID>>>(Wih, bih, bhh);
    }

    final_kernel<<<BATCH * HID / 256, 256>>>((float*)d_out, out_size);
}

// round 11
// speedup vs baseline: 4.5686x; 2.5678x over previous
#include <cuda_runtime.h>
#include <cuda_fp16.h>
#include <math.h>
#include <stdint.h>
#include <mma.h>

using namespace nvcuda;

#define BATCH 2048
#define HID   512
#define WIN   24
#define LZ    514   // HID + KERNEL - 1

// ==================== scratch (device globals; no allocations) ====================
__device__ float  g_H   [(size_t)WIN * BATCH * HID];   // fp32 H (for ctpart)
__device__ __half g_Hh  [(size_t)WIN * BATCH * HID];   // fp16 H (GEMM operand)
__device__ float  g_HiUd[(size_t)WIN * BATCH * HID];
__device__ float  g_X   [(size_t)BATCH * 1024];        // fp32 [d|s] (output)
__device__ __half g_Xh  [(size_t)BATCH * 1024];        // fp16 [d|s] (GEMM operand)
__device__ float  g_G   [(size_t)BATCH * 2048];
__device__ float  g_lp  [4 * BATCH];
__device__ float  g_yr  [BATCH];
__device__ float  g_yf  [BATCH];
__device__ float  g_ctv [HID];
__device__ float  g_part[32 * HID];
__device__ unsigned int g_cnt;
__device__ __half g_Wdh [512 * 1024];
__device__ __half g_Udh [512 * 512];
__device__ __half g_Whhh[2048 * 512];

// ==================== fp16 GEMM body: 128x128 tile, BK=64, 512 threads (16 warps 4x4) ====================
// Warp tile 32x32 -> 2x2 m16n16k16 fp16 frags (fp32 accum). Double-buffered smem, reg prefetch.
// MODE 0: C = A@B^T (fp32 out).
// MODE 1: T = A@B^T + add; lp[row] = sum_c tanh(T[row,c])*vd[col0+c].
#define SLDH  72                          // half stride (64 + 8 pad)
#define BUFH  (128 * SLDH)                // 9216 halves per buffer
#define SLT   132                         // fp32 epilogue tile stride
#define GEMM_SMEM_BYTES (4 * BUFH * 2)    // 73728 bytes (>= 128*SLT*4 = 67584)

template<int MODE>
__device__ __forceinline__ void gemm_body_h(
    const __half* __restrict__ A, int lda,
    const __half* __restrict__ B, int ldb,
    float*        __restrict__ C, int ldc,
    const float*  __restrict__ addP, int ldadd,
    const float*  __restrict__ vd, float* __restrict__ lpOut,
    int K, int row0, int col0, __half* smem)
{
    const int tid = threadIdx.x, wid = tid >> 5, lane = tid & 31;
    const int warpM = wid & 3, warpN = wid >> 2;           // 4 x 4
    const int rb_ = tid >> 3;                              // 0..63
    const int cb_ = (tid & 7) * 8;                         // halves: 0,8,..,56

    const __half* Aptr = A + (size_t)(row0 + rb_) * lda + cb_;
    const __half* Bptr = B + (size_t)(col0 + rb_) * ldb + cb_;

    wmma::fragment<wmma::accumulator, 16, 16, 16, float> acc[2][2];
    #pragma unroll
    for (int mi = 0; mi < 2; mi++)
        #pragma unroll
        for (int ni = 0; ni < 2; ni++)
            wmma::fill_fragment(acc[mi][ni], 0.f);

    uint4 ra[2], rb4[2];
    #pragma unroll
    for (int i = 0; i < 2; i++) {
        ra[i]  = *(const uint4*)(Aptr + (size_t)(i * 64) * lda);
        rb4[i] = *(const uint4*)(Bptr + (size_t)(i * 64) * ldb);
    }
    {
        __half* sA = smem;
        __half* sB = smem + 2 * BUFH;
        #pragma unroll
        for (int i = 0; i < 2; i++) {
            *(uint4*)&sA[(rb_ + i * 64) * SLDH + cb_] = ra[i];
            *(uint4*)&sB[(rb_ + i * 64) * SLDH + cb_] = rb4[i];
        }
    }
    __syncthreads();

    const int nk = K >> 6;
    for (int kc = 0; kc < nk; kc++) {
        const int cur = kc & 1;
        const bool more = (kc + 1 < nk);
        if (more) {
            const int k0 = (kc + 1) << 6;
            #pragma unroll
            for (int i = 0; i < 2; i++) {
                ra[i]  = *(const uint4*)(Aptr + (size_t)(i * 64) * lda + k0);
                rb4[i] = *(const uint4*)(Bptr + (size_t)(i * 64) * ldb + k0);
            }
        }
        const __half* sA = smem + cur * BUFH;
        const __half* sB = smem + 2 * BUFH + cur * BUFH;
        #pragma unroll
        for (int kk = 0; kk < 4; kk++) {                   // 4 x (K=16)
            wmma::fragment<wmma::matrix_a, 16, 16, 16, __half, wmma::row_major> af[2];
            wmma::fragment<wmma::matrix_b, 16, 16, 16, __half, wmma::col_major> bf[2];
            #pragma unroll
            for (int mi = 0; mi < 2; mi++)
                wmma::load_matrix_sync(af[mi], &sA[(warpM * 32 + mi * 16) * SLDH + kk * 16], SLDH);
            #pragma unroll
            for (int ni = 0; ni < 2; ni++)
                wmma::load_matrix_sync(bf[ni], &sB[(warpN * 32 + ni * 16) * SLDH + kk * 16], SLDH);
            #pragma unroll
            for (int mi = 0; mi < 2; mi++)
                #pragma unroll
                for (int ni = 0; ni < 2; ni++)
                    wmma::mma_sync(acc[mi][ni], af[mi], bf[ni], acc[mi][ni]);
        }
        if (more) {
            __half* dA = smem + (cur ^ 1) * BUFH;
            __half* dB = smem + 2 * BUFH + (cur ^ 1) * BUFH;
            #pragma unroll
            for (int i = 0; i < 2; i++) {
                *(uint4*)&dA[(rb_ + i * 64) * SLDH + cb_] = ra[i];
                *(uint4*)&dB[(rb_ + i * 64) * SLDH + cb_] = rb4[i];
            }
        }
        __syncthreads();
    }

    if (MODE == 0) {
        #pragma unroll
        for (int mi = 0; mi < 2; mi++)
            #pragma unroll
            for (int ni = 0; ni < 2; ni++)
                wmma::store_matrix_sync(
                    C + (size_t)(row0 + warpM * 32 + mi * 16) * ldc
                      + col0 + warpN * 32 + ni * 16,
                    acc[mi][ni], ldc, wmma::mem_row_major);
    } else {
        float* smf = (float*)smem;
        #pragma unroll
        for (int mi = 0; mi < 2; mi++) {
            #pragma unroll
            for (int ni = 0; ni < 2; ni++) {
                int rr = row0 + warpM * 32 + mi * 16;
                int cc = col0 + warpN * 32 + ni * 16;
                wmma::fragment<wmma::accumulator, 16, 16, 16, float> ad;
                wmma::load_matrix_sync(ad, addP + (size_t)rr * ldadd + cc, ldadd, wmma::mem_row_major);
                #pragma unroll
                for (int e = 0; e < acc[mi][ni].num_elements; e++)
                    acc[mi][ni].x[e] += ad.x[e];
                wmma::store_matrix_sync(
                    &smf[(warpM * 32 + mi * 16) * SLT + warpN * 32 + ni * 16],
                    acc[mi][ni], SLT, wmma::mem_row_major);
            }
        }
        __syncthreads();
        float4 vdv = *(const float4*)(vd + col0 + lane * 4);
        #pragma unroll
        for (int r8 = 0; r8 < 8; r8++) {
            int row = wid * 8 + r8;
            float4 v = *(const float4*)&smf[row * SLT + lane * 4];
            float s = tanhf(v.x) * vdv.x + tanhf(v.y) * vdv.y
                    + tanhf(v.z) * vdv.z + tanhf(v.w) * vdv.w;
            #pragma unroll
            for (int o = 16; o; o >>= 1) s += __shfl_xor_sync(0xFFFFFFFFu, s, o);
            if (!lane) lpOut[row0 + row] = s;
        }
    }
}

// ---- fused per-step GEMM: blocks 0..63 = L-gemm (dot mode), 64..319 = G-gemm ----
__global__ __launch_bounds__(512) void step_gemm(
    const float* __restrict__ HiUd_t,
    const float* __restrict__ vd)
{
    extern __shared__ __half smem[];
    int id = blockIdx.x;
    if (id < 64) {
        int bx = id & 3, by = id >> 2;       // 4 col-tiles x 16 row-tiles
        gemm_body_h<1>(g_Xh, 1024, g_Wdh, 1024, nullptr, 0, HiUd_t, 512,
                       vd, g_lp + bx * BATCH, 1024, by * 128, bx * 128, smem);
    } else {
        id -= 64;
        int bx = id & 15, by = id >> 4;      // 16 x 16
        gemm_body_h<0>(g_Xh, 1024, g_Whhh, 512, g_G, 2048, nullptr, 0,
                       nullptr, nullptr, 512, by * 128, bx * 128, smem);
    }
}

// ---- precompute GEMM: HiUd = H @ Ud^T ----
__global__ __launch_bounds__(512) void gemm_pre()
{
    extern __shared__ __half smem[];
    gemm_body_h<0>(g_Hh, 512, g_Udh, 512, g_HiUd, 512, nullptr, 0,
                   nullptr, nullptr, 512, blockIdx.y * 128, blockIdx.x * 128, smem);
}

// ==================== weight conversion (once per launch) ====================
__global__ void convert_weights(const float* __restrict__ Wd,
                                const float* __restrict__ Ud,
                                const float* __restrict__ Whh)
{
    size_t i = (size_t)blockIdx.x * blockDim.x + threadIdx.x;   // 2048*512 threads
    if (i < (size_t)512 * 1024) g_Wdh[i]  = __float2half(Wd[i]);
    if (i < (size_t)512 * 512)  g_Udh[i]  = __float2half(Ud[i]);
    g_Whhh[i] = __float2half(Whh[i]);
}

// ==================== conv + relu (fp32 + fp16 outputs) ====================
__global__ void conv_kernel(const float* __restrict__ Z,
                            const float* __restrict__ conv_w,
                            const float* __restrict__ conv_b)
{
    int b = blockIdx.x;
    int h = threadIdx.x;
    __shared__ float z0[LZ + 2];
    __shared__ float z1[LZ + 2];
    const float* Z0 = Z + (size_t)b * LZ;
    const float* Z1 = Z + (size_t)(BATCH + b) * LZ;
    for (int i = h; i < LZ; i += HID) { z0[i] = Z0[i]; z1[i] = Z1[i]; }
    __syncthreads();
    float a0 = z0[h], a1 = z0[h + 1], a2 = z0[h + 2];
    float b0 = z1[h], b1 = z1[h + 1], b2 = z1[h + 2];
    #pragma unroll
    for (int t = 0; t < WIN; t++) {
        const float* cw = conv_w + t * 6;
        float v = conv_b[t]
                + a0 * cw[0] + a1 * cw[1] + a2 * cw[2]
                + b0 * cw[3] + b1 * cw[4] + b2 * cw[5];
        v = fmaxf(v, 0.f);
        size_t idx = ((size_t)t * BATCH + b) * HID + h;
        g_H[idx]  = v;
        g_Hh[idx] = __float2half(v);
    }
}

// ==================== fused: softmax(l) + partial Bw@H[t] + last-block yfake ====================
__global__ void smax_ct_yfake_kernel(int t, const float* __restrict__ w)
{
    __shared__ float sl[BATCH];
    __shared__ float red[16];
    __shared__ float sv[2];
    const int tid = threadIdx.x;         // 512
    const int wid = tid >> 5, lane = tid & 31;

    for (int i = tid; i < BATCH; i += 512)
        sl[i] = g_lp[i] + g_lp[BATCH + i] + g_lp[2 * BATCH + i] + g_lp[3 * BATCH + i];
    __syncthreads();

    float m = -1e30f;
    for (int i = tid; i < BATCH; i += 512) m = fmaxf(m, sl[i]);
    #pragma unroll
    for (int o = 16; o; o >>= 1) m = fmaxf(m, __shfl_xor_sync(0xFFFFFFFFu, m, o));
    if (!lane) red[wid] = m;
    __syncthreads();
    if (tid < 32) {
        float v = (tid < 16) ? red[tid] : -1e30f;
        #pragma unroll
        for (int o = 16; o; o >>= 1) v = fmaxf(v, __shfl_xor_sync(0xFFFFFFFFu, v, o));
        if (!tid) sv[0] = v;
    }
    __syncthreads();
    m = sv[0];
    float s = 0.f;
    for (int i = tid; i < BATCH; i += 512) s += expf(sl[i] - m);
    #pragma unroll
    for (int o = 16; o; o >>= 1) s += __shfl_xor_sync(0xFFFFFFFFu, s, o);
    if (!lane) red[wid] = s;
    __syncthreads();
    if (tid < 32) {
        float v = (tid < 16) ? red[tid] : 0.f;
        #pragma unroll
        for (int o = 16; o; o >>= 1) v += __shfl_xor_sync(0xFFFFFFFFu, v, o);
        if (!tid) sv[1] = v;
    }
    __syncthreads();
    const float inv = 1.f / sv[1];

    const int h = tid, blk = blockIdx.x;
    const float* Ht = g_H + (size_t)t * BATCH * HID;
    float acc = 0.f;
    const int b0 = blk * 64;
    for (int b = b0; b < b0 + 64; b++)
        acc = fmaf(expf(sl[b] - m) * inv, Ht[(size_t)b * HID + h], acc);
    g_part[blk * HID + h] = acc;
    __threadfence();

    __shared__ bool last;
    if (h == 0) {
        unsigned v = atomicAdd(&g_cnt, 1u);
        last = (v == 31u);
    }
    __syncthreads();
    if (!last) return;
    if (h == 0) g_cnt = 0u;

    __shared__ float ysh;
    float cv = g_ctv[h];
    #pragma unroll
    for (int i = 0; i < 32; i++) cv += g_part[i * HID + h];
    g_ctv[h] = cv;
    float p = cv * w[WIN + h];
    #pragma unroll
    for (int o = 16; o; o >>= 1) p += __shfl_xor_sync(0xFFFFFFFFu, p, o);
    if (!lane) red[wid] = p;
    __syncthreads();
    if (tid < 32) {
        float v = (tid < 16) ? red[tid] : 0.f;
        #pragma unroll
        for (int o = 16; o; o >>= 1) v += __shfl_xor_sync(0xFFFFFFFFu, v, o);
        if (!tid) ysh = v;
    }
    __syncthreads();
    const float ys = ysh;
    for (int b = h; b < BATCH; b += 512) g_yf[b] = g_yr[b] + ys;
}

// ==================== LSTM cell update (writes fp32 + fp16 state) ====================
__device__ __forceinline__ float sigf(float x) { return 1.f / (1.f + expf(-x)); }

__global__ void lstm_kernel(const float* __restrict__ Wih,
                            const float* __restrict__ bih,
                            const float* __restrict__ bhh)
{
    int b = blockIdx.x, h = threadIdx.x;
    float y = g_yf[b];
    const float* g = g_G + (size_t)b * 2048;
    float ig = sigf (fmaf(y, Wih[h],           bih[h]           + bhh[h])           + g[h]);
    float fg = sigf (fmaf(y, Wih[HID + h],     bih[HID + h]     + bhh[HID + h])     + g[HID + h]);
    float gg = tanhf(fmaf(y, Wih[2*HID + h],   bih[2*HID + h]   + bhh[2*HID + h])   + g[2*HID + h]);
    float og = sigf (fmaf(y, Wih[3*HID + h],   bih[3*HID + h]   + bhh[3*HID + h])   + g[3*HID + h]);
    float* X = g_X + (size_t)b * 1024;
    float ns = fg * X[HID + h] + ig * gg;
    float nd = og * tanhf(ns);
    X[h] = nd;
    X[HID + h] = ns;
    g_Xh[(size_t)b * 1024 + h]       = __float2half(nd);
    g_Xh[(size_t)b * 1024 + HID + h] = __float2half(ns);
}

// ==================== init ====================
__global__ void init_kernel(const float* __restrict__ din,
                            const float* __restrict__ sin_,
                            const float* __restrict__ y_real,
                            const float* __restrict__ w,
                            const float* __restrict__ bparam)
{
    size_t i = (size_t)blockIdx.x * blockDim.x + threadIdx.x;
    int b = (int)(i / HID), h = (int)(i % HID);
    float dv = din[i], sv_ = sin_[i];
    g_X[(size_t)b * 1024 + h]        = dv;
    g_X[(size_t)b * 1024 + HID + h]  = sv_;
    g_Xh[(size_t)b * 1024 + h]       = __float2half(dv);
    g_Xh[(size_t)b * 1024 + HID + h] = __float2half(sv_);
    if (i < HID) g_ctv[i] = 0.f;
    if (i == 0)  g_cnt = 0u;
    if (i < BATCH) {
        float s = bparam[0];
        #pragma unroll
        for (int k = 0; k < WIN; k++) s = fmaf(y_real[i * WIN + k], w[k], s);
        g_yr[i] = s;
    }
}

// ==================== finalize ====================
__global__ void final_kernel(float* __restrict__ out, int out_size)
{
    size_t i = (size_t)blockIdx.x * blockDim.x + threadIdx.x;
    if (i < BATCH && i < (size_t)out_size) out[i] = g_yf[i];
    if (out_size >= BATCH + 2 * BATCH * HID) {
        int b = (int)(i / HID), h = (int)(i % HID);
        out[BATCH + i]               = g_X[(size_t)b * 1024 + h];
        out[BATCH + BATCH * HID + i] = g_X[(size_t)b * 1024 + HID + h];
    }
}

// ==================== launch ====================
extern "C" void kernel_launch(void* const* d_in, const int* in_sizes, int n_in,
                              void* d_out, int out_size)
{
    const float* Z      = (const float*)d_in[0];
    const float* din    = (const float*)d_in[1];
    const float* sin_   = (const float*)d_in[2];
    const float* y_real = (const float*)d_in[3];
    const float* vd     = (const float*)d_in[4];
    const float* Wd     = (const float*)d_in[5];
    const float* Ud     = (const float*)d_in[6];
    const float* w      = (const float*)d_in[7];
    const float* bparam = (const float*)d_in[8];
    const float* conv_w = (const float*)d_in[9];
    const float* conv_b = (const float*)d_in[10];
    const float* Wih    = (const float*)d_in[11];
    const float* Whh    = (const float*)d_in[12];
    const float* bih    = (const float*)d_in[13];
    const float* bhh    = (const float*)d_in[14];

    float* pHiUd;
    cudaGetSymbolAddress((void**)&pHiUd, g_HiUd);

    cudaFuncSetAttribute(step_gemm, cudaFuncAttributeMaxDynamicSharedMemorySize, GEMM_SMEM_BYTES);
    cudaFuncSetAttribute(gemm_pre,  cudaFuncAttributeMaxDynamicSharedMemorySize, GEMM_SMEM_BYTES);

    convert_weights<<<2048 * 512 / 256, 256>>>(Wd, Ud, Whh);
    conv_kernel<<<BATCH, HID>>>(Z, conv_w, conv_b);
    gemm_pre<<<dim3(HID / 128, WIN * BATCH / 128), 512, GEMM_SMEM_BYTES>>>();
    init_kernel<<<BATCH * HID / 256, 256>>>(din, sin_, y_real, w, bparam);

    for (int t = 0; t < WIN; t++) {
        step_gemm<<<320, 512, GEMM_SMEM_BYTES>>>(
            pHiUd + (size_t)t * BATCH * HID, vd);
        smax_ct_yfake_kernel<<<32, HID>>>(t, w);
        lstm_kernel<<<BATCH, HID>>>(Wih, bih, bhh);
    }

    final_kernel<<<BATCH * HID / 256, 256>>>((float*)d_out, out_size);
}

// round 17
// speedup vs baseline: 4.5847x; 1.0035x over previous
#include <cuda_runtime.h>
#include <cuda_fp16.h>
#include <math.h>
#include <stdint.h>
#include <mma.h>

using namespace nvcuda;

#define BATCH 2048
#define HID   512
#define WIN   24
#define LZ    514   // HID + KERNEL - 1

// ==================== scratch (device globals; no allocations) ====================
__device__ __half g_Hh   [(size_t)WIN * BATCH * HID];   // fp16 H (GEMM + ctpart)
__device__ __half g_HiUdh[(size_t)WIN * BATCH * HID];   // fp16 H @ Ud^T
__device__ float  g_X    [(size_t)BATCH * 1024];        // fp32 [d|s] (output precision)
__device__ __half g_Xh   [(size_t)BATCH * 1024];        // fp16 [d|s] (GEMM operand)
__device__ __half g_Gh   [(size_t)BATCH * 2048];        // fp16 d0 @ Whh^T
__device__ float  g_lp   [4 * BATCH];
__device__ float  g_yr   [BATCH];
__device__ float  g_yf   [BATCH];
__device__ float  g_ctv  [HID];
__device__ float  g_part [32 * HID];
__device__ unsigned int g_cnt;
__device__ __half g_Wdh  [512 * 1024];
__device__ __half g_Udh  [512 * 512];
__device__ __half g_Whhh [2048 * 512];

// ==================== fp16 GEMM body: 128x128 tile, BK=64, 512 threads (16 warps 4x4) ====================
// Warp tile 32x32 -> 2x2 m16n16k16 fp16 frags (fp32 accum). Double-buffered smem, reg prefetch.
// MODE 1: T = A@B^T + addH; lp[row] = sum_c tanh(T[row,c])*vd[col0+c]  (no C store).
// MODE 2: Ch = (half)(A@B^T)  (coalesced half2 store via smem spill).
#define SLDH  72                          // half stride (64 + 8 pad)
#define BUFH  (128 * SLDH)                // 9216 halves per buffer
#define SLT   132                         // fp32 epilogue tile stride
#define GEMM_SMEM_BYTES (4 * BUFH * 2)    // 73728 bytes (>= 128*SLT*4 = 67584)

template<int MODE>
__device__ __forceinline__ void gemm_body_h(
    const __half* __restrict__ A, int lda,
    const __half* __restrict__ B, int ldb,
    __half*       __restrict__ Ch, int ldc,
    const __half* __restrict__ addH,
    const float*  __restrict__ vd, float* __restrict__ lpOut,
    int K, int row0, int col0, __half* smem)
{
    const int tid = threadIdx.x, wid = tid >> 5, lane = tid & 31;
    const int warpM = wid & 3, warpN = wid >> 2;           // 4 x 4
    const int rb_ = tid >> 3;                              // 0..63
    const int cb_ = (tid & 7) * 8;                         // halves: 0,8,..,56

    const __half* Aptr = A + (size_t)(row0 + rb_) * lda + cb_;
    const __half* Bptr = B + (size_t)(col0 + rb_) * ldb + cb_;

    wmma::fragment<wmma::accumulator, 16, 16, 16, float> acc[2][2];
    #pragma unroll
    for (int mi = 0; mi < 2; mi++)
        #pragma unroll
        for (int ni = 0; ni < 2; ni++)
            wmma::fill_fragment(acc[mi][ni], 0.f);

    uint4 ra[2], rb4[2];
    #pragma unroll
    for (int i = 0; i < 2; i++) {
        ra[i]  = *(const uint4*)(Aptr + (size_t)(i * 64) * lda);
        rb4[i] = *(const uint4*)(Bptr + (size_t)(i * 64) * ldb);
    }
    {
        __half* sA = smem;
        __half* sB = smem + 2 * BUFH;
        #pragma unroll
        for (int i = 0; i < 2; i++) {
            *(uint4*)&sA[(rb_ + i * 64) * SLDH + cb_] = ra[i];
            *(uint4*)&sB[(rb_ + i * 64) * SLDH + cb_] = rb4[i];
        }
    }
    __syncthreads();

    const int nk = K >> 6;
    for (int kc = 0; kc < nk; kc++) {
        const int cur = kc & 1;
        const bool more = (kc + 1 < nk);
        if (more) {
            const int k0 = (kc + 1) << 6;
            #pragma unroll
            for (int i = 0; i < 2; i++) {
                ra[i]  = *(const uint4*)(Aptr + (size_t)(i * 64) * lda + k0);
                rb4[i] = *(const uint4*)(Bptr + (size_t)(i * 64) * ldb + k0);
            }
        }
        const __half* sA = smem + cur * BUFH;
        const __half* sB = smem + 2 * BUFH + cur * BUFH;
        #pragma unroll
        for (int kk = 0; kk < 4; kk++) {                   // 4 x (K=16)
            wmma::fragment<wmma::matrix_a, 16, 16, 16, __half, wmma::row_major> af[2];
            wmma::fragment<wmma::matrix_b, 16, 16, 16, __half, wmma::col_major> bf[2];
            #pragma unroll
            for (int mi = 0; mi < 2; mi++)
                wmma::load_matrix_sync(af[mi], &sA[(warpM * 32 + mi * 16) * SLDH + kk * 16], SLDH);
            #pragma unroll
            for (int ni = 0; ni < 2; ni++)
                wmma::load_matrix_sync(bf[ni], &sB[(warpN * 32 + ni * 16) * SLDH + kk * 16], SLDH);
            #pragma unroll
            for (int mi = 0; mi < 2; mi++)
                #pragma unroll
                for (int ni = 0; ni < 2; ni++)
                    wmma::mma_sync(acc[mi][ni], af[mi], bf[ni], acc[mi][ni]);
        }
        if (more) {
            __half* dA = smem + (cur ^ 1) * BUFH;
            __half* dB = smem + 2 * BUFH + (cur ^ 1) * BUFH;
            #pragma unroll
            for (int i = 0; i < 2; i++) {
                *(uint4*)&dA[(rb_ + i * 64) * SLDH + cb_] = ra[i];
                *(uint4*)&dB[(rb_ + i * 64) * SLDH + cb_] = rb4[i];
            }
        }
        __syncthreads();
    }

    // spill fp32 tile to smem (raw A@B^T)
    float* smf = (float*)smem;
    #pragma unroll
    for (int mi = 0; mi < 2; mi++)
        #pragma unroll
        for (int ni = 0; ni < 2; ni++)
            wmma::store_matrix_sync(
                &smf[(warpM * 32 + mi * 16) * SLT + warpN * 32 + ni * 16],
                acc[mi][ni], SLT, wmma::mem_row_major);
    __syncthreads();

    if (MODE == 2) {
        // convert + coalesced half2 store: warp wid handles rows wid*8..+7
        #pragma unroll
        for (int r8 = 0; r8 < 8; r8++) {
            int row = wid * 8 + r8;
            float4 v = *(const float4*)&smf[row * SLT + lane * 4];
            half2 h0 = __floats2half2_rn(v.x, v.y);
            half2 h1 = __floats2half2_rn(v.z, v.w);
            __half* dst = Ch + (size_t)(row0 + row) * ldc + col0 + lane * 4;
            *(half2*)dst       = h0;
            *((half2*)dst + 1) = h1;
        }
    } else {
        // MODE 1: add HiUd (fp16, direct coords), tanh, dot with vd
        float4 vdv = *(const float4*)(vd + col0 + lane * 4);
        #pragma unroll
        for (int r8 = 0; r8 < 8; r8++) {
            int row = wid * 8 + r8;
            float4 v = *(const float4*)&smf[row * SLT + lane * 4];
            const __half* hp = addH + (size_t)(row0 + row) * HID + col0 + lane * 4;
            half2 a01 = *(const half2*)hp;
            half2 a23 = *((const half2*)hp + 1);
            v.x += __low2float(a01);  v.y += __high2float(a01);
            v.z += __low2float(a23);  v.w += __high2float(a23);
            float s = tanhf(v.x) * vdv.x + tanhf(v.y) * vdv.y
                    + tanhf(v.z) * vdv.z + tanhf(v.w) * vdv.w;
            #pragma unroll
            for (int o = 16; o; o >>= 1) s += __shfl_xor_sync(0xFFFFFFFFu, s, o);
            if (!lane) lpOut[row0 + row] = s;
        }
    }
}

// ---- fused per-step GEMM: blocks 0..63 = L-gemm (dot mode), 64..319 = G-gemm ----
__global__ __launch_bounds__(512) void step_gemm(
    const __half* __restrict__ HiUd_t,
    const float*  __restrict__ vd)
{
    extern __shared__ __half smem[];
    int id = blockIdx.x;
    if (id < 64) {
        int bx = id & 3, by = id >> 2;       // 4 col-tiles x 16 row-tiles
        gemm_body_h<1>(g_Xh, 1024, g_Wdh, 1024, nullptr, 0, HiUd_t,
                       vd, g_lp + bx * BATCH, 1024, by * 128, bx * 128, smem);
    } else {
        id -= 64;
        int bx = id & 15, by = id >> 4;      // 16 x 16
        gemm_body_h<2>(g_Xh, 1024, g_Whhh, 512, g_Gh, 2048, nullptr,
                       nullptr, nullptr, 512, by * 128, bx * 128, smem);
    }
}

// ---- precompute GEMM: HiUdh = (half)(H @ Ud^T) ----
__global__ __launch_bounds__(512) void gemm_pre()
{
    extern __shared__ __half smem[];
    gemm_body_h<2>(g_Hh, 512, g_Udh, 512, g_HiUdh, 512, nullptr,
                   nullptr, nullptr, 512, blockIdx.y * 128, blockIdx.x * 128, smem);
}

// ==================== weight conversion (once per launch) ====================
__global__ void convert_weights(const float* __restrict__ Wd,
                                const float* __restrict__ Ud,
                                const float* __restrict__ Whh)
{
    size_t i = (size_t)blockIdx.x * blockDim.x + threadIdx.x;   // 2048*512 threads
    if (i < (size_t)512 * 1024) g_Wdh[i]  = __float2half(Wd[i]);
    if (i < (size_t)512 * 512)  g_Udh[i]  = __float2half(Ud[i]);
    g_Whhh[i] = __float2half(Whh[i]);
}

// ==================== conv + relu (fp16 output only) ====================
__global__ void conv_kernel(const float* __restrict__ Z,
                            const float* __restrict__ conv_w,
                            const float* __restrict__ conv_b)
{
    int b = blockIdx.x;
    int h = threadIdx.x;
    __shared__ float z0[LZ + 2];
    __shared__ float z1[LZ + 2];
    const float* Z0 = Z + (size_t)b * LZ;
    const float* Z1 = Z + (size_t)(BATCH + b) * LZ;
    for (int i = h; i < LZ; i += HID) { z0[i] = Z0[i]; z1[i] = Z1[i]; }
    __syncthreads();
    float a0 = z0[h], a1 = z0[h + 1], a2 = z0[h + 2];
    float b0 = z1[h], b1 = z1[h + 1], b2 = z1[h + 2];
    #pragma unroll
    for (int t = 0; t < WIN; t++) {
        const float* cw = conv_w + t * 6;
        float v = conv_b[t]
                + a0 * cw[0] + a1 * cw[1] + a2 * cw[2]
                + b0 * cw[3] + b1 * cw[4] + b2 * cw[5];
        g_Hh[((size_t)t * BATCH + b) * HID + h] = __float2half(fmaxf(v, 0.f));
    }
}

// ==================== fused: softmax(l) + partial Bw@H[t] + last-block yfake ====================
__global__ void smax_ct_yfake_kernel(int t, const float* __restrict__ w)
{
    __shared__ float sl[BATCH];
    __shared__ float red[16];
    __shared__ float sv[2];
    const int tid = threadIdx.x;         // 512
    const int wid = tid >> 5, lane = tid & 31;

    for (int i = tid; i < BATCH; i += 512)
        sl[i] = g_lp[i] + g_lp[BATCH + i] + g_lp[2 * BATCH + i] + g_lp[3 * BATCH + i];
    __syncthreads();

    float m = -1e30f;
    for (int i = tid; i < BATCH; i += 512) m = fmaxf(m, sl[i]);
    #pragma unroll
    for (int o = 16; o; o >>= 1) m = fmaxf(m, __shfl_xor_sync(0xFFFFFFFFu, m, o));
    if (!lane) red[wid] = m;
    __syncthreads();
    if (tid < 32) {
        float v = (tid < 16) ? red[tid] : -1e30f;
        #pragma unroll
        for (int o = 16; o; o >>= 1) v = fmaxf(v, __shfl_xor_sync(0xFFFFFFFFu, v, o));
        if (!tid) sv[0] = v;
    }
    __syncthreads();
    m = sv[0];
    float s = 0.f;
    for (int i = tid; i < BATCH; i += 512) s += expf(sl[i] - m);
    #pragma unroll
    for (int o = 16; o; o >>= 1) s += __shfl_xor_sync(0xFFFFFFFFu, s, o);
    if (!lane) red[wid] = s;
    __syncthreads();
    if (tid < 32) {
        float v = (tid < 16) ? red[tid] : 0.f;
        #pragma unroll
        for (int o = 16; o; o >>= 1) v += __shfl_xor_sync(0xFFFFFFFFu, v, o);
        if (!tid) sv[1] = v;
    }
    __syncthreads();
    const float inv = 1.f / sv[1];

    // ctpart: this block's 64 batch rows, fp16 H (fixed order -> deterministic)
    const int h = tid, blk = blockIdx.x;
    const __half* Ht = g_Hh + (size_t)t * BATCH * HID;
    float acc = 0.f;
    const int b0 = blk * 64;
    for (int b = b0; b < b0 + 64; b++)
        acc = fmaf(expf(sl[b] - m) * inv, __half2float(Ht[(size_t)b * HID + h]), acc);
    g_part[blk * HID + h] = acc;
    __threadfence();

    __shared__ bool last;
    if (h == 0) {
        unsigned v = atomicAdd(&g_cnt, 1u);
        last = (v == 31u);
    }
    __syncthreads();
    if (!last) return;
    if (h == 0) g_cnt = 0u;

    __shared__ float ysh;
    float cv = g_ctv[h];
    #pragma unroll
    for (int i = 0; i < 32; i++) cv += g_part[i * HID + h];
    g_ctv[h] = cv;
    float p = cv * w[WIN + h];
    #pragma unroll
    for (int o = 16; o; o >>= 1) p += __shfl_xor_sync(0xFFFFFFFFu, p, o);
    if (!lane) red[wid] = p;
    __syncthreads();
    if (tid < 32) {
        float v = (tid < 16) ? red[tid] : 0.f;
        #pragma unroll
        for (int o = 16; o; o >>= 1) v += __shfl_xor_sync(0xFFFFFFFFu, v, o);
        if (!tid) ysh = v;
    }
    __syncthreads();
    const float ys = ysh;
    for (int b = h; b < BATCH; b += 512) g_yf[b] = g_yr[b] + ys;
}

// ==================== LSTM cell update (fp16 G in; fp32 + fp16 state out) ====================
__device__ __forceinline__ float sigf(float x) { return 1.f / (1.f + expf(-x)); }

__global__ void lstm_kernel(const float* __restrict__ Wih,
                            const float* __restrict__ bih,
                            const float* __restrict__ bhh)
{
    int b = blockIdx.x, h = threadIdx.x;
    float y = g_yf[b];
    const __half* g = g_Gh + (size_t)b * 2048;
    float g0 = __half2float(g[h]);
    float g1 = __half2float(g[HID + h]);
    float g2 = __half2float(g[2 * HID + h]);
    float g3 = __half2float(g[3 * HID + h]);
    float ig = sigf (fmaf(y, Wih[h],         bih[h]         + bhh[h])         + g0);
    float fg = sigf (fmaf(y, Wih[HID + h],   bih[HID + h]   + bhh[HID + h])   + g1);
    float gg = tanhf(fmaf(y, Wih[2*HID + h], bih[2*HID + h] + bhh[2*HID + h]) + g2);
    float og = sigf (fmaf(y, Wih[3*HID + h], bih[3*HID + h] + bhh[3*HID + h]) + g3);
    float* X = g_X + (size_t)b * 1024;
    float ns = fg * X[HID + h] + ig * gg;
    float nd = og * tanhf(ns);
    X[h] = nd;
    X[HID + h] = ns;
    g_Xh[(size_t)b * 1024 + h]       = __float2half(nd);
    g_Xh[(size_t)b * 1024 + HID + h] = __float2half(ns);
}

// ==================== init ====================
__global__ void init_kernel(const float* __restrict__ din,
                            const float* __restrict__ sin_,
                            const float* __restrict__ y_real,
                            const float* __restrict__ w,
                            const float* __restrict__ bparam)
{
    size_t i = (size_t)blockIdx.x * blockDim.x + threadIdx.x;
    int b = (int)(i / HID), h = (int)(i % HID);
    float dv = din[i], sv_ = sin_[i];
    g_X[(size_t)b * 1024 + h]        = dv;
    g_X[(size_t)b * 1024 + HID + h]  = sv_;
    g_Xh[(size_t)b * 1024 + h]       = __float2half(dv);
    g_Xh[(size_t)b * 1024 + HID + h] = __float2half(sv_);
    if (i < HID) g_ctv[i] = 0.f;
    if (i == 0)  g_cnt = 0u;
    if (i < BATCH) {
        float s = bparam[0];
        #pragma unroll
        for (int k = 0; k < WIN; k++) s = fmaf(y_real[i * WIN + k], w[k], s);
        g_yr[i] = s;
    }
}

// ==================== finalize ====================
__global__ void final_kernel(float* __restrict__ out, int out_size)
{
    size_t i = (size_t)blockIdx.x * blockDim.x + threadIdx.x;
    if (i < BATCH && i < (size_t)out_size) out[i] = g_yf[i];
    if (out_size >= BATCH + 2 * BATCH * HID) {
        int b = (int)(i / HID), h = (int)(i % HID);
        out[BATCH + i]               = g_X[(size_t)b * 1024 + h];
        out[BATCH + BATCH * HID + i] = g_X[(size_t)b * 1024 + HID + h];
    }
}

// ==================== launch ====================
extern "C" void kernel_launch(void* const* d_in, const int* in_sizes, int n_in,
                              void* d_out, int out_size)
{
    const float* Z      = (const float*)d_in[0];
    const float* din    = (const float*)d_in[1];
    const float* sin_   = (const float*)d_in[2];
    const float* y_real = (const float*)d_in[3];
    const float* vd     = (const float*)d_in[4];
    const float* Wd     = (const float*)d_in[5];
    const float* Ud     = (const float*)d_in[6];
    const float* w      = (const float*)d_in[7];
    const float* bparam = (const float*)d_in[8];
    const float* conv_w = (const float*)d_in[9];
    const float* conv_b = (const float*)d_in[10];
    const float* Wih    = (const float*)d_in[11];
    const float* Whh    = (const float*)d_in[12];
    const float* bih    = (const float*)d_in[13];
    const float* bhh    = (const float*)d_in[14];

    __half* pHiUdh;
    cudaGetSymbolAddress((void**)&pHiUdh, g_HiUdh);

    cudaFuncSetAttribute(step_gemm, cudaFuncAttributeMaxDynamicSharedMemorySize, GEMM_SMEM_BYTES);
    cudaFuncSetAttribute(gemm_pre,  cudaFuncAttributeMaxDynamicSharedMemorySize, GEMM_SMEM_BYTES);

    convert_weights<<<2048 * 512 / 256, 256>>>(Wd, Ud, Whh);
    conv_kernel<<<BATCH, HID>>>(Z, conv_w, conv_b);
    gemm_pre<<<dim3(HID / 128, WIN * BATCH / 128), 512, GEMM_SMEM_BYTES>>>();
    init_kernel<<<BATCH * HID / 256, 256>>>(din, sin_, y_real, w, bparam);

    for (int t = 0; t < WIN; t++) {
        step_gemm<<<320, 512, GEMM_SMEM_BYTES>>>(
            pHiUdh + (size_t)t * BATCH * HID, vd);
        smax_ct_yfake_kernel<<<32, HID>>>(t, w);
        lstm_kernel<<<BATCH, HID>>>(Wih, bih, bhh);
    }

    final_kernel<<<BATCH * HID / 256, 256>>>((float*)d_out, out_size);
}